// round 4
// baseline (speedup 1.0000x reference)
#include <cuda_runtime.h>
#include <cuda_bf16.h>
#include <mma.h>
#include <math.h>

using namespace nvcuda;

// ---------------- problem constants ----------------
#define BB    64
#define PP    196
#define ENC   512
#define EE    1024
#define HH    1024
#define AA    512
#define VV    20000
#define LL    25
#define TT    24

// ---------------- scratch layout (floats) ----------------
#define OFF_ATT_ENC  0u            // 12544*512
#define OFF_EBIAS    6422528u      // 1536*4096
#define OFF_WREC     12713984u     // 1536*4096
#define OFF_WIH      19005440u     // 1024*4096
#define OFF_WCAT     23199744u     // 1024*1024
#define OFF_BCAT     24248320u     // 1024
#define OFF_BREC     24249344u     // 4096
#define OFF_MEAN     24253440u     // 64*512
#define OFF_SX       24286208u     // 2 * 64*1536
#define OFF_C        24482816u     // 64*1024
#define OFF_ATTDEC   24548352u     // 64*1024
#define OFF_HALL     24613888u     // 1536*1024
#define SCRATCH_TOTAL 26186752u

__device__ __align__(256) float g_scratch[SCRATCH_TOTAL];

__device__ unsigned g_bar_count = 0;
__device__ unsigned g_bar_gen   = 0;

__device__ __forceinline__ float4 tf32x4(float4 v)
{
    v.x = wmma::__float_to_tf32(v.x);
    v.y = wmma::__float_to_tf32(v.y);
    v.z = wmma::__float_to_tf32(v.z);
    v.w = wmma::__float_to_tf32(v.w);
    return v;
}

// ---------------- prep: pack / permute weights ----------------
__global__ void prep_kernel(const float* __restrict__ Wdec, const float* __restrict__ Wfb,
                            const float* __restrict__ bdec, const float* __restrict__ bfb,
                            const float* __restrict__ Wih,  const float* __restrict__ Whh,
                            const float* __restrict__ bih,  const float* __restrict__ bhh)
{
    float* Wcat = g_scratch + OFF_WCAT;
    float* bcat = g_scratch + OFF_BCAT;
    float* Wrec = g_scratch + OFF_WREC;
    float* Wihp = g_scratch + OFF_WIH;
    float* brec = g_scratch + OFF_BREC;

    int i = blockIdx.x * blockDim.x + threadIdx.x;
    int stride = gridDim.x * blockDim.x;

    for (int idx = i; idx < 1024 * 1024; idx += stride) {
        int k = idx >> 10, c = idx & 1023;
        Wcat[idx] = (c < 512) ? Wdec[k * 512 + c] : Wfb[k * 512 + (c - 512)];
    }
    for (int idx = i; idx < 1024; idx += stride)
        bcat[idx] = (idx < 512) ? bdec[idx] : bfb[idx - 512];

    for (int idx = i; idx < 1536 * 4096; idx += stride) {
        int r = idx >> 12, cp = idx & 4095;
        int j = cp >> 2, q = cp & 3;
        int oc = q * 1024 + j;
        Wrec[idx] = (r < 512) ? Wih[(size_t)(1024 + r) * 4096 + oc]
                              : Whh[(size_t)(r - 512) * 4096 + oc];
    }
    for (int idx = i; idx < 1024 * 4096; idx += stride) {
        int r = idx >> 12, cp = idx & 4095;
        int j = cp >> 2, q = cp & 3;
        Wihp[idx] = Wih[(size_t)r * 4096 + q * 1024 + j];
    }
    for (int idx = i; idx < 4096; idx += stride) {
        int j = idx >> 2, q = idx & 3;
        brec[idx] = bih[q * 1024 + j] + bhh[q * 1024 + j];
    }
}

// ---------------- mean over P ----------------
__global__ void mean_kernel(const float* __restrict__ enc)
{
    int b = blockIdx.x;
    float* mean = g_scratch + OFF_MEAN;
    for (int e = threadIdx.x; e < ENC; e += blockDim.x) {
        float s = 0.f;
        const float* base = enc + (size_t)(b * PP) * ENC + e;
        #pragma unroll 4
        for (int p = 0; p < PP; ++p) s += base[(size_t)p * ENC];
        mean[b * ENC + e] = s * (1.f / (float)PP);
    }
}

// ================= big tf32 GEMM: 128x128 tile, GBK=32, pre-rounded staging =================
// AMODE 0: plain A (row-clamped);  2: rows gathered from emb via caps
// CMODE 0: plain C;  1: preds remap m=t*64+b -> C[(b*24+t)][n]
#define ASTRIDE 36
#define BSTRIDE 132
#define ABUF   (128 * ASTRIDE)     // 4608
#define BBUF   (32 * BSTRIDE)      // 4224
#define BG_SMEM_FLOATS (2 * ABUF + 2 * BBUF)

template<int AMODE, int CMODE>
__global__ __launch_bounds__(256)
void big_gemm(const float* __restrict__ A, int lda,
              const float* __restrict__ emb, const int* __restrict__ caps,
              const float* __restrict__ B, int ldb,
              float* __restrict__ C, int ldc,
              const float* __restrict__ bias,
              int M, int N, int K)
{
    extern __shared__ float dyn[];
    float* As = dyn;                 // [2][128][36]
    float* Bs = dyn + 2 * ABUF;      // [2][32][132]
    __shared__ int scap[128];

    const int tid = threadIdx.x;
    const int n0 = blockIdx.x * 128;
    const int m0 = blockIdx.y * 128;

    if (AMODE == 2) {
        if (tid < 128) {
            int m = m0 + tid;
            int tt = m >> 6, bb = m & 63;
            scap[tid] = caps[bb * LL + tt];
        }
        __syncthreads();
    }

    const int wid = tid >> 5;
    const int wr = wid & 3;            // 4 m-chunks of 32
    const int wc = wid >> 2;           // 2 n-chunks of 64

    const int ar = tid >> 1, ac = (tid & 1) * 16;
    const int br = tid >> 3, bc = (tid & 7) * 16;

    const float* A0;
    if (AMODE == 0) {
        int r = m0 + ar; if (r >= M) r = M - 1;
        A0 = A + (size_t)r * lda + ac;
    } else {
        A0 = emb + (size_t)scap[ar] * EE + ac;
    }
    const float* B0 = B + (size_t)br * ldb + n0 + bc;
    bool bval[4];
    #pragma unroll
    for (int i = 0; i < 4; ++i) bval[i] = (n0 + bc + i * 4) < N;

    wmma::fragment<wmma::accumulator, 16, 16, 8, float> acc[2][4];
    #pragma unroll
    for (int i = 0; i < 2; ++i)
        #pragma unroll
        for (int j = 0; j < 4; ++j) wmma::fill_fragment(acc[i][j], 0.f);

    const int nk = K >> 5;

    float4 pa[4], pb[4];
    #pragma unroll
    for (int i = 0; i < 4; ++i) {
        pa[i] = *(const float4*)(A0 + i * 4);
        pb[i] = bval[i] ? *(const float4*)(B0 + i * 4) : make_float4(0, 0, 0, 0);
    }
    #pragma unroll
    for (int i = 0; i < 4; ++i) {
        *(float4*)&As[ar * ASTRIDE + ac + i * 4] = tf32x4(pa[i]);
        *(float4*)&Bs[br * BSTRIDE + bc + i * 4] = tf32x4(pb[i]);
    }
    __syncthreads();

    for (int kt = 0; kt < nk; ++kt) {
        int buf = kt & 1;
        if (kt + 1 < nk) {
            int ko = (kt + 1) * 32;
            #pragma unroll
            for (int i = 0; i < 4; ++i) {
                pa[i] = *(const float4*)(A0 + ko + i * 4);
                pb[i] = bval[i] ? *(const float4*)(B0 + (size_t)ko * ldb + i * 4)
                                : make_float4(0, 0, 0, 0);
            }
        }
        const float* Ab = As + buf * ABUF;
        const float* Bb = Bs + buf * BBUF;
        #pragma unroll
        for (int ks = 0; ks < 4; ++ks) {
            wmma::fragment<wmma::matrix_a, 16, 16, 8, wmma::precision::tf32, wmma::row_major> af[2];
            wmma::fragment<wmma::matrix_b, 16, 16, 8, wmma::precision::tf32, wmma::row_major> bf[4];
            #pragma unroll
            for (int i = 0; i < 2; ++i)
                wmma::load_matrix_sync(af[i], Ab + (wr * 32 + i * 16) * ASTRIDE + ks * 8, ASTRIDE);
            #pragma unroll
            for (int j = 0; j < 4; ++j)
                wmma::load_matrix_sync(bf[j], Bb + (ks * 8) * BSTRIDE + wc * 64 + j * 16, BSTRIDE);
            #pragma unroll
            for (int i = 0; i < 2; ++i)
                #pragma unroll
                for (int j = 0; j < 4; ++j)
                    wmma::mma_sync(acc[i][j], af[i], bf[j], acc[i][j]);
        }
        if (kt + 1 < nk) {
            int nb = buf ^ 1;
            #pragma unroll
            for (int i = 0; i < 4; ++i) {
                *(float4*)&As[nb * ABUF + ar * ASTRIDE + ac + i * 4] = tf32x4(pa[i]);
                *(float4*)&Bs[nb * BBUF + br * BSTRIDE + bc + i * 4] = tf32x4(pb[i]);
            }
        }
        __syncthreads();
    }

    // epilogue: 4 chunks of 32 rows through smem
    float* Cs = dyn;  // 32 x 132
    for (int chunk = 0; chunk < 4; ++chunk) {
        if (wr == chunk) {
            #pragma unroll
            for (int i = 0; i < 2; ++i)
                #pragma unroll
                for (int j = 0; j < 4; ++j)
                    wmma::store_matrix_sync(Cs + (i * 16) * BSTRIDE + wc * 64 + j * 16,
                                            acc[i][j], BSTRIDE, wmma::mem_row_major);
        }
        __syncthreads();
        #pragma unroll
        for (int it = 0; it < 16; ++it) {
            int idx = tid + it * 256;
            int r = idx >> 7, cn = idx & 127;
            int m = m0 + chunk * 32 + r;
            int n = n0 + cn;
            if (m < M && n < N) {
                float v = Cs[r * BSTRIDE + cn] + bias[n];
                if (CMODE == 0) {
                    C[(size_t)m * ldc + n] = v;
                } else {
                    int bb = m & 63, tt = m >> 6;
                    C[((size_t)bb * TT + tt) * ldc + n] = v;
                }
            }
        }
        __syncthreads();
    }
}

// ================= persistent recurrence kernel =================
#define NBLK 128

__device__ __forceinline__ void grid_sync(unsigned& gen)
{
    __syncthreads();
    if (threadIdx.x == 0) {
        __threadfence();
        unsigned arrived = atomicAdd(&g_bar_count, 1u);
        if (arrived == (unsigned)(NBLK - 1)) {
            g_bar_count = 0;
            __threadfence();
            atomicAdd(&g_bar_gen, 1u);
        } else {
            while (*(volatile unsigned*)&g_bar_gen == gen) __nanosleep(64);
            __threadfence();
        }
    }
    gen++;
    __syncthreads();
}

// 64x32 wmma gemm, GBK=32, double buffered, pre-rounded staging.
__device__ __forceinline__ void tile_gemm_64x32(
    const float* __restrict__ A, int lda,
    const float* __restrict__ B, int ldb, int K,
    float* sbuf,
    wmma::fragment<wmma::accumulator, 16, 16, 8, float>& acc)
{
    const int tid = threadIdx.x;
    const int wid = tid >> 5, wr = wid & 3, wc = wid >> 2;
    float* As = sbuf;           // [2][64][36]
    float* Bs = sbuf + 4608;    // [2][32][36]
    const int ar = tid >> 3, ac = (tid & 7) * 4;

    const float* Ap0 = A + (size_t)ar * lda + ac;
    const float* Ap1 = A + (size_t)(ar + 32) * lda + ac;
    const float* Bp  = B + (size_t)ar * ldb + ac;

    const int nk = K >> 5;
    float4 a0 = *(const float4*)(Ap0);
    float4 a1 = *(const float4*)(Ap1);
    float4 b0 = *(const float4*)(Bp);
    *(float4*)&As[ar * 36 + ac]        = tf32x4(a0);
    *(float4*)&As[(ar + 32) * 36 + ac] = tf32x4(a1);
    *(float4*)&Bs[ar * 36 + ac]        = tf32x4(b0);
    __syncthreads();

    for (int kt = 0; kt < nk; ++kt) {
        int buf = kt & 1;
        if (kt + 1 < nk) {
            int ko = (kt + 1) * 32;
            a0 = *(const float4*)(Ap0 + ko);
            a1 = *(const float4*)(Ap1 + ko);
            b0 = *(const float4*)(Bp + (size_t)ko * ldb);
        }
        const float* Ab = As + buf * 2304;
        const float* Bb = Bs + buf * 1152;
        #pragma unroll
        for (int kk = 0; kk < 4; ++kk) {
            wmma::fragment<wmma::matrix_a, 16, 16, 8, wmma::precision::tf32, wmma::row_major> af;
            wmma::fragment<wmma::matrix_b, 16, 16, 8, wmma::precision::tf32, wmma::row_major> bf;
            wmma::load_matrix_sync(af, Ab + (wr * 16) * 36 + kk * 8, 36);
            wmma::load_matrix_sync(bf, Bb + (kk * 8) * 36 + wc * 16, 36);
            wmma::mma_sync(acc, af, bf, acc);
        }
        if (kt + 1 < nk) {
            int nb = buf ^ 1;
            *(float4*)&As[nb * 2304 + ar * 36 + ac]        = tf32x4(a0);
            *(float4*)&As[nb * 2304 + (ar + 32) * 36 + ac] = tf32x4(a1);
            *(float4*)&Bs[nb * 1152 + ar * 36 + ac]        = tf32x4(b0);
        }
        __syncthreads();
    }
}

__device__ __forceinline__ float sigm(float x) { return 1.f / (1.f + expf(-x)); }

__global__ __launch_bounds__(256, 1)
void recur_kernel(const float* __restrict__ enc,
                  const float* __restrict__ wfull,
                  const float* __restrict__ bfull,
                  float* __restrict__ alpha_out)
{
    __shared__ float sbuf[6912];

    const int bi = blockIdx.x;
    const int tid = threadIdx.x;
    const int wid = tid >> 5, lane = tid & 31;

    float* S = g_scratch;
    const float* att_enc = S + OFF_ATT_ENC;
    const float* Wcat    = S + OFF_WCAT;
    const float* bcat    = S + OFF_BCAT;
    const float* Wrec    = S + OFF_WREC;
    const float* ebias   = S + OFF_EBIAS;
    float* sx            = S + OFF_SX;
    float* cbuf          = S + OFF_C;
    float* attdec        = S + OFF_ATTDEC;
    float* hall          = S + OFF_HALL;

    unsigned gen = *(volatile unsigned*)&g_bar_gen;
    const float bf0 = bfull[0];

    for (int t = 0; t < TT; ++t) {
        const int cur = t & 1, nxt = cur ^ 1;
        float* sxc = sx + cur * (64 * 1536);
        float* sxn = sx + nxt * (64 * 1536);

        // ---- P1: attdec = h @ Wcat + bcat (blocks 0..31) ----
        if (bi < 32) {
            wmma::fragment<wmma::accumulator, 16, 16, 8, float> acc;
            wmma::fill_fragment(acc, 0.f);
            tile_gemm_64x32(sxc + 512, 1536, Wcat + bi * 32, 1024, HH, sbuf, acc);
            const int wr = wid & 3, wc = wid >> 2;
            wmma::store_matrix_sync(sbuf + (wr * 16) * 36 + wc * 16, acc, 36, wmma::mem_row_major);
            __syncthreads();
            const int n0 = bi * 32;
            #pragma unroll
            for (int i = 0; i < 8; ++i) {
                int idx = tid + i * 256;
                int r = idx >> 5, c = idx & 31;
                attdec[r * 1024 + n0 + c] = sbuf[r * 36 + c] + bcat[n0 + c];
            }
        }
        grid_sync(gen);

        // ---- P2: attention (blocks 0..63) ----
        if (bi < 64) {
            const int b = bi;
            float* sa = sbuf;
            float* sw = sbuf + 512;
            float* se = sbuf + 1024;
            float* sred = sbuf + 1224;

            for (int i = tid; i < AA; i += 256) {
                sa[i] = attdec[b * 1024 + i];
                sw[i] = wfull[i];
            }
            __syncthreads();

            for (int p = wid; p < PP; p += 8) {
                const float* row = att_enc + (size_t)(b * PP + p) * AA;
                float acc = 0.f;
                #pragma unroll 4
                for (int a = lane; a < AA; a += 32) {
                    float x = row[a] + sa[a];
                    x = x > 0.f ? x : 0.f;
                    acc += x * sw[a];
                }
                #pragma unroll
                for (int o = 16; o; o >>= 1) acc += __shfl_xor_sync(0xffffffffu, acc, o);
                if (lane == 0) se[p] = acc + bf0;
            }
            __syncthreads();

            float v = (tid < PP) ? se[tid] : -1e30f;
            float m = v;
            #pragma unroll
            for (int o = 16; o; o >>= 1) m = fmaxf(m, __shfl_xor_sync(0xffffffffu, m, o));
            if (lane == 0) sred[wid] = m;
            __syncthreads();
            if (wid == 0) {
                float mm = (lane < 8) ? sred[lane] : -1e30f;
                #pragma unroll
                for (int o = 16; o; o >>= 1) mm = fmaxf(mm, __shfl_xor_sync(0xffffffffu, mm, o));
                if (lane == 0) sred[0] = mm;
            }
            __syncthreads();
            float mx = sred[0];
            __syncthreads();

            float ex = (tid < PP) ? expf(v - mx) : 0.f;
            float s = ex;
            #pragma unroll
            for (int o = 16; o; o >>= 1) s += __shfl_xor_sync(0xffffffffu, s, o);
            if (lane == 0) sred[wid] = s;
            __syncthreads();
            if (wid == 0) {
                float ss = (lane < 8) ? sred[lane] : 0.f;
                #pragma unroll
                for (int o = 16; o; o >>= 1) ss += __shfl_xor_sync(0xffffffffu, ss, o);
                if (lane == 0) sred[0] = ss;
            }
            __syncthreads();
            float inv = 1.f / sred[0];

            if (tid < PP) {
                float al = ex * inv;
                se[tid] = al;
                alpha_out[((size_t)b * TT + t) * PP + tid] = al;
            }
            __syncthreads();

            for (int e = tid; e < ENC; e += 256) {
                const float* col = enc + (size_t)(b * PP) * ENC + e;
                float acc = 0.f;
                #pragma unroll 4
                for (int p = 0; p < PP; ++p) acc += se[p] * col[(size_t)p * ENC];
                float fb = attdec[b * 1024 + 512 + e];
                sxc[b * 1536 + e] = sigm(fb) * acc;
            }
        }
        grid_sync(gen);

        // ---- P3: gates + fused LSTM (all 128 blocks) ----
        {
            wmma::fragment<wmma::accumulator, 16, 16, 8, float> acc;
            wmma::fill_fragment(acc, 0.f);
            const int n0 = bi * 32;
            tile_gemm_64x32(sxc, 1536, Wrec + n0, 4096, ENC + HH, sbuf, acc);
            const int wr = wid & 3, wc = wid >> 2;
            wmma::store_matrix_sync(sbuf + (wr * 16) * 36 + wc * 16, acc, 36, wmma::mem_row_major);
            __syncthreads();

            #pragma unroll
            for (int i = 0; i < 2; ++i) {
                int p = tid + i * 256;
                int b = p >> 3, jj = p & 7;
                int j = bi * 8 + jj;
                float4 g = *(float4*)&sbuf[b * 36 + jj * 4];
                float4 e = *(const float4*)&ebias[((size_t)t * BB + b) * 4096 + n0 + jj * 4];
                float gi = g.x + e.x, gf = g.y + e.y, gg = g.z + e.z, go = g.w + e.w;
                float co = cbuf[b * 1024 + j];
                float cn = sigm(gf) * co + sigm(gi) * tanhf(gg);
                float h  = sigm(go) * tanhf(cn);
                cbuf[b * 1024 + j] = cn;
                sxn[b * 1536 + 512 + j] = h;
                hall[((size_t)t * BB + b) * 1024 + j] = h;
            }
        }
        grid_sync(gen);
    }
}

// ---------------- launch ----------------
extern "C" void kernel_launch(void* const* d_in, const int* in_sizes, int n_in,
                              void* d_out, int out_size)
{
    const float* enc       = (const float*)d_in[0];
    const int*   caps      = (const int*)  d_in[1];
    const float* W_enc_att = (const float*)d_in[3];
    const float* b_enc_att = (const float*)d_in[4];
    const float* W_dec_att = (const float*)d_in[5];
    const float* b_dec_att = (const float*)d_in[6];
    const float* W_full    = (const float*)d_in[7];
    const float* b_full    = (const float*)d_in[8];
    const float* emb       = (const float*)d_in[9];
    const float* W_ih      = (const float*)d_in[10];
    const float* b_ih      = (const float*)d_in[11];
    const float* W_hh      = (const float*)d_in[12];
    const float* b_hh      = (const float*)d_in[13];
    const float* W_init_h  = (const float*)d_in[14];
    const float* b_init_h  = (const float*)d_in[15];
    const float* W_init_c  = (const float*)d_in[16];
    const float* b_init_c  = (const float*)d_in[17];
    const float* W_fbeta   = (const float*)d_in[18];
    const float* b_fbeta   = (const float*)d_in[19];
    const float* W_fc      = (const float*)d_in[20];
    const float* b_fc      = (const float*)d_in[21];

    float* out = (float*)d_out;
    float* alpha_out = out + (size_t)BB * TT * VV;

    void* sp = nullptr;
    cudaGetSymbolAddress(&sp, g_scratch);
    float* S = (float*)sp;

    const int smemB = BG_SMEM_FLOATS * sizeof(float);   // ~70 KB
    cudaFuncSetAttribute(big_gemm<0, 0>, cudaFuncAttributeMaxDynamicSharedMemorySize, smemB);
    cudaFuncSetAttribute(big_gemm<2, 0>, cudaFuncAttributeMaxDynamicSharedMemorySize, smemB);
    cudaFuncSetAttribute(big_gemm<0, 1>, cudaFuncAttributeMaxDynamicSharedMemorySize, smemB);

    prep_kernel<<<1024, 256>>>(W_dec_att, W_fbeta, b_dec_att, b_fbeta, W_ih, W_hh, b_ih, b_hh);
    mean_kernel<<<BB, 256>>>(enc);

    big_gemm<0, 0><<<dim3(8, 1), 256, smemB>>>(S + OFF_MEAN, ENC, nullptr, nullptr,
                                               W_init_h, HH, S + OFF_SX + 512, 1536,
                                               b_init_h, BB, HH, ENC);
    big_gemm<0, 0><<<dim3(8, 1), 256, smemB>>>(S + OFF_MEAN, ENC, nullptr, nullptr,
                                               W_init_c, HH, S + OFF_C, HH,
                                               b_init_c, BB, HH, ENC);

    big_gemm<0, 0><<<dim3(4, 98), 256, smemB>>>(enc, ENC, nullptr, nullptr,
                                                W_enc_att, AA, S + OFF_ATT_ENC, AA,
                                                b_enc_att, BB * PP, AA, ENC);

    big_gemm<2, 0><<<dim3(32, 12), 256, smemB>>>(nullptr, 0, emb, caps,
                                                 S + OFF_WIH, 4096, S + OFF_EBIAS, 4096,
                                                 S + OFF_BREC, TT * BB, 4096, EE);

    recur_kernel<<<NBLK, 256>>>(enc, W_full, b_full, alpha_out);

    big_gemm<0, 1><<<dim3(157, 12), 256, smemB>>>(S + OFF_HALL, HH, nullptr, nullptr,
                                                  W_fc, VV, out, VV,
                                                  b_fc, TT * BB, VV, HH);
}

// round 6
// speedup vs baseline: 1.2080x; 1.2080x over previous
#include <cuda_runtime.h>
#include <cuda_bf16.h>
#include <mma.h>
#include <math.h>
#include <cstdint>

using namespace nvcuda;

// ---------------- problem constants ----------------
#define BB    64
#define PP    196
#define ENC   512
#define EE    1024
#define HH    1024
#define AA    512
#define VV    20000
#define LL    25
#define TT    24

// ---------------- scratch layout (floats) ----------------
#define OFF_ATT_ENC  0u            // 12544*512
#define OFF_EBIAS    6422528u      // 1536*4096
#define OFF_WREC     12713984u     // 1536*4096 (tf32-rounded, col-permuted)
#define OFF_WIH      19005440u     // 1024*4096 (tf32-rounded, col-permuted)
#define OFF_WCAT     23199744u     // 1024*1024 (tf32-rounded)
#define OFF_BCAT     24248320u     // 1024
#define OFF_BREC     24249344u     // 4096
#define OFF_MEAN     24253440u     // 64*512 (tf32-rounded)
#define OFF_SX       24286208u     // 2 * 64*1536 (tf32-rounded [gc|h])
#define OFF_C        24482816u     // 64*1024 (fp32)
#define OFF_ATTDEC   24548352u     // 64*1024 (fp32)
#define OFF_HALL     24613888u     // 1536*1024 (tf32-rounded)
#define OFF_ENC_R    26186752u     // 12544*512 tf32-rounded enc
#define OFF_EMB_R    32609280u     // 20000*1024 tf32-rounded emb
#define OFF_WFC_R    53089280u     // 1024*20000 tf32-rounded W_fc
#define OFF_WEA_R    73569280u     // 512*512
#define OFF_WIH0     73831424u     // 512*1024
#define OFF_WIC0     74355712u     // 512*1024
#define SCRATCH_TOTAL 74880000u

__device__ __align__(256) float g_scratch[SCRATCH_TOTAL];

__device__ unsigned g_bar_count = 0;
__device__ unsigned g_bar_gen   = 0;

__device__ __forceinline__ float tf32r(float x) { return wmma::__float_to_tf32(x); }

// ---------------- prep: pack / permute / pre-round weights ----------------
__global__ void prep_kernel(const float* __restrict__ Wdec, const float* __restrict__ Wfb,
                            const float* __restrict__ bdec, const float* __restrict__ bfb,
                            const float* __restrict__ Wih,  const float* __restrict__ Whh,
                            const float* __restrict__ bih,  const float* __restrict__ bhh,
                            const float* __restrict__ enc,  const float* __restrict__ emb,
                            const float* __restrict__ Wfc,  const float* __restrict__ Wea,
                            const float* __restrict__ Wih0, const float* __restrict__ Wic0)
{
    float* Wcat = g_scratch + OFF_WCAT;
    float* bcat = g_scratch + OFF_BCAT;
    float* Wrec = g_scratch + OFF_WREC;
    float* Wihp = g_scratch + OFF_WIH;
    float* brec = g_scratch + OFF_BREC;
    float* encr = g_scratch + OFF_ENC_R;
    float* embr = g_scratch + OFF_EMB_R;
    float* wfcr = g_scratch + OFF_WFC_R;
    float* wear = g_scratch + OFF_WEA_R;
    float* wih0 = g_scratch + OFF_WIH0;
    float* wic0 = g_scratch + OFF_WIC0;

    int i = blockIdx.x * blockDim.x + threadIdx.x;
    int stride = gridDim.x * blockDim.x;

    for (int idx = i; idx < 1024 * 1024; idx += stride) {
        int k = idx >> 10, c = idx & 1023;
        Wcat[idx] = tf32r((c < 512) ? Wdec[k * 512 + c] : Wfb[k * 512 + (c - 512)]);
    }
    for (int idx = i; idx < 1024; idx += stride)
        bcat[idx] = (idx < 512) ? bdec[idx] : bfb[idx - 512];

    for (int idx = i; idx < 1536 * 4096; idx += stride) {
        int r = idx >> 12, cp = idx & 4095;
        int j = cp >> 2, q = cp & 3;
        int oc = q * 1024 + j;
        Wrec[idx] = tf32r((r < 512) ? Wih[(size_t)(1024 + r) * 4096 + oc]
                                    : Whh[(size_t)(r - 512) * 4096 + oc]);
    }
    for (int idx = i; idx < 1024 * 4096; idx += stride) {
        int r = idx >> 12, cp = idx & 4095;
        int j = cp >> 2, q = cp & 3;
        Wihp[idx] = tf32r(Wih[(size_t)r * 4096 + q * 1024 + j]);
    }
    for (int idx = i; idx < 4096; idx += stride) {
        int j = idx >> 2, q = idx & 3;
        brec[idx] = bih[q * 1024 + j] + bhh[q * 1024 + j];
    }
    for (int idx = i; idx < BB * PP * ENC; idx += stride) encr[idx] = tf32r(enc[idx]);
    for (int idx = i; idx < VV * EE;       idx += stride) embr[idx] = tf32r(emb[idx]);
    for (int idx = i; idx < HH * VV;       idx += stride) wfcr[idx] = tf32r(Wfc[idx]);
    for (int idx = i; idx < ENC * AA;      idx += stride) wear[idx] = tf32r(Wea[idx]);
    for (int idx = i; idx < ENC * HH;      idx += stride) wih0[idx] = tf32r(Wih0[idx]);
    for (int idx = i; idx < ENC * HH;      idx += stride) wic0[idx] = tf32r(Wic0[idx]);
}

// ---------------- mean over P (tf32-rounded output) ----------------
__global__ void mean_kernel(const float* __restrict__ enc)
{
    int b = blockIdx.x;
    float* mean = g_scratch + OFF_MEAN;
    for (int e = threadIdx.x; e < ENC; e += blockDim.x) {
        float s = 0.f;
        const float* base = enc + (size_t)(b * PP) * ENC + e;
        #pragma unroll 4
        for (int p = 0; p < PP; ++p) s += base[(size_t)p * ENC];
        mean[b * ENC + e] = tf32r(s * (1.f / (float)PP));
    }
}

// ================= gemm2: 128x128 tile, 4 warps (64x64), cp.async 3-stage =================
// All operands PRE-ROUNDED to tf32 in gmem: raw async copies, no in-kernel conversion.
// AMODE 0: plain A (row-clamped);  2: rows gathered from emb_r via caps
// CMODE 0: plain C;  1: preds remap m=t*64+b -> C[(b*24+t)][n]
// CROUND: round stored value to tf32 (when C is a future GEMM A operand)
#define NS   3
#define G2BM 128
#define G2BN 128
#define G2BK 32
#define G2ASTR 36
#define G2BSTR 132
#define G2ASZ (G2BM * G2ASTR)     // 4608
#define G2BSZ (G2BK * G2BSTR)     // 4224
#define G2STG (G2ASZ + G2BSZ)     // 8832 floats
#define G2_SMEM_BYTES (NS * G2STG * 4)   // 105984

__device__ __forceinline__ void cp16(unsigned int dst, const float* src, int pred)
{
    asm volatile(
        "{\n\t.reg .pred p;\n\t"
        "setp.ne.b32 p, %2, 0;\n\t"
        "@p cp.async.cg.shared.global [%0], [%1], 16;\n\t}\n"
        :: "r"(dst), "l"(src), "r"(pred));
}

template<int AMODE, int CMODE, int CROUND>
__global__ __launch_bounds__(128, 2)
void gemm2(const float* __restrict__ A, int lda,
           const float* __restrict__ emb, const int* __restrict__ caps,
           const float* __restrict__ B, int ldb,
           float* __restrict__ C, int ldc,
           const float* __restrict__ bias,
           int M, int N, int K)
{
    extern __shared__ float dyn[];
    __shared__ int scap[G2BM];

    const int tid = threadIdx.x;
    const int n0 = blockIdx.x * G2BN;
    const int m0 = blockIdx.y * G2BM;

    if (AMODE == 2) {
        int m = m0 + tid;
        int tt = m >> 6, bb = m & 63;
        scap[tid] = caps[bb * LL + tt];
        __syncthreads();
    }

    // per-thread copy chunks: 8 for A (q = tid + i*128), 8 for B
    const float* arow[8];
    const float* brow[8];
    int bval[8];
    #pragma unroll
    for (int i = 0; i < 8; ++i) {
        int q = tid + i * 128;
        int r = q >> 3;                    // 0..127
        if (AMODE == 0) {
            int gr = m0 + r; if (gr >= M) gr = M - 1;
            arow[i] = A + (size_t)gr * lda;
        } else {
            arow[i] = emb + (size_t)scap[r] * EE;
        }
        int br = q >> 5;                   // 0..31
        int bcn = (q & 31) * 4;            // 0..124
        brow[i] = B + (size_t)br * ldb + n0 + bcn;
        bval[i] = (n0 + bcn) < N;
    }
    const unsigned int sbase = (unsigned int)__cvta_generic_to_shared(dyn);

    auto load_stage = [&](int kt, int s) {
        const unsigned int so = sbase + (unsigned int)(s * G2STG) * 4u;
        const int k0 = kt * G2BK;
        #pragma unroll
        for (int i = 0; i < 8; ++i) {
            int q = tid + i * 128;
            int r = q >> 3, c = (q & 7) * 4;
            cp16(so + (unsigned int)(r * G2ASTR + c) * 4u, arow[i] + k0 + c, 1);
        }
        #pragma unroll
        for (int i = 0; i < 8; ++i) {
            int q = tid + i * 128;
            int br = q >> 5, bcn = (q & 31) * 4;
            cp16(so + (unsigned int)(G2ASZ + br * G2BSTR + bcn) * 4u,
                 brow[i] + (size_t)k0 * ldb, bval[i]);
        }
        asm volatile("cp.async.commit_group;\n" ::: "memory");
    };

    const int nk = K / G2BK;
    #pragma unroll
    for (int s = 0; s < NS - 1; ++s) load_stage(s, s);

    const int wid = tid >> 5;
    const int wr = wid & 1;       // 2 m-halves of 64
    const int wc = wid >> 1;      // 2 n-halves of 64

    wmma::fragment<wmma::accumulator, 16, 16, 8, float> acc[4][4];
    #pragma unroll
    for (int i = 0; i < 4; ++i)
        #pragma unroll
        for (int j = 0; j < 4; ++j) wmma::fill_fragment(acc[i][j], 0.f);

    for (int kt = 0; kt < nk; ++kt) {
        asm volatile("cp.async.wait_group 1;\n" ::: "memory");
        __syncthreads();

        if (kt + NS - 1 < nk) load_stage(kt + NS - 1, (kt + NS - 1) % NS);
        else asm volatile("cp.async.commit_group;\n" ::: "memory");

        const float* Ab = dyn + (kt % NS) * G2STG;
        const float* Bb = Ab + G2ASZ;
        #pragma unroll
        for (int ks = 0; ks < 4; ++ks) {
            wmma::fragment<wmma::matrix_a, 16, 16, 8, wmma::precision::tf32, wmma::row_major> af[4];
            wmma::fragment<wmma::matrix_b, 16, 16, 8, wmma::precision::tf32, wmma::row_major> bf[4];
            #pragma unroll
            for (int i = 0; i < 4; ++i)
                wmma::load_matrix_sync(af[i], Ab + (wr * 64 + i * 16) * G2ASTR + ks * 8, G2ASTR);
            #pragma unroll
            for (int j = 0; j < 4; ++j)
                wmma::load_matrix_sync(bf[j], Bb + (ks * 8) * G2BSTR + wc * 64 + j * 16, G2BSTR);
            #pragma unroll
            for (int i = 0; i < 4; ++i)
                #pragma unroll
                for (int j = 0; j < 4; ++j)
                    wmma::mma_sync(acc[i][j], af[i], bf[j], acc[i][j]);
        }
    }
    asm volatile("cp.async.wait_group 0;\n" ::: "memory");
    __syncthreads();

    // epilogue: two 64-row halves staged through smem
    float* Cs = dyn;   // 64 x G2BSTR
    for (int half = 0; half < 2; ++half) {
        if (wr == half) {
            #pragma unroll
            for (int i = 0; i < 4; ++i)
                #pragma unroll
                for (int j = 0; j < 4; ++j)
                    wmma::store_matrix_sync(Cs + (i * 16) * G2BSTR + wc * 64 + j * 16,
                                            acc[i][j], G2BSTR, wmma::mem_row_major);
        }
        __syncthreads();
        #pragma unroll
        for (int it = 0; it < 64; ++it) {
            int idx = tid + it * 128;
            int r = idx >> 7, cn = idx & 127;
            int m = m0 + half * 64 + r;
            int n = n0 + cn;
            if (m < M && n < N) {
                float v = Cs[r * G2BSTR + cn] + bias[n];
                if (CROUND) v = tf32r(v);
                if (CMODE == 0) {
                    C[(size_t)m * ldc + n] = v;
                } else {
                    int bb = m & 63, tt = m >> 6;
                    C[((size_t)bb * TT + tt) * ldc + n] = v;
                }
            }
        }
        __syncthreads();
    }
}

// ================= persistent recurrence kernel =================
#define NBLK 128

__device__ __forceinline__ void grid_sync(unsigned& gen)
{
    __syncthreads();
    if (threadIdx.x == 0) {
        __threadfence();
        unsigned arrived = atomicAdd(&g_bar_count, 1u);
        if (arrived == (unsigned)(NBLK - 1)) {
            g_bar_count = 0;
            __threadfence();
            atomicAdd(&g_bar_gen, 1u);
        } else {
            while (*(volatile unsigned*)&g_bar_gen == gen) __nanosleep(64);
            __threadfence();
        }
    }
    gen++;
    __syncthreads();
}

// 64x32 wmma gemm, GBK=32, double buffered; operands pre-rounded -> raw loads.
__device__ __forceinline__ void tile_gemm_64x32(
    const float* __restrict__ A, int lda,
    const float* __restrict__ B, int ldb, int K,
    float* sbuf,
    wmma::fragment<wmma::accumulator, 16, 16, 8, float>& acc)
{
    const int tid = threadIdx.x;
    const int wid = tid >> 5, wr = wid & 3, wc = wid >> 2;
    float* As = sbuf;           // [2][64][36]
    float* Bs = sbuf + 4608;    // [2][32][36]
    const int ar = tid >> 3, ac = (tid & 7) * 4;

    const float* Ap0 = A + (size_t)ar * lda + ac;
    const float* Ap1 = A + (size_t)(ar + 32) * lda + ac;
    const float* Bp  = B + (size_t)ar * ldb + ac;

    const int nk = K >> 5;
    float4 a0 = *(const float4*)(Ap0);
    float4 a1 = *(const float4*)(Ap1);
    float4 b0 = *(const float4*)(Bp);
    *(float4*)&As[ar * 36 + ac]        = a0;
    *(float4*)&As[(ar + 32) * 36 + ac] = a1;
    *(float4*)&Bs[ar * 36 + ac]        = b0;
    __syncthreads();

    for (int kt = 0; kt < nk; ++kt) {
        int buf = kt & 1;
        if (kt + 1 < nk) {
            int ko = (kt + 1) * 32;
            a0 = *(const float4*)(Ap0 + ko);
            a1 = *(const float4*)(Ap1 + ko);
            b0 = *(const float4*)(Bp + (size_t)ko * ldb);
        }
        const float* Ab = As + buf * 2304;
        const float* Bb = Bs + buf * 1152;
        #pragma unroll
        for (int kk = 0; kk < 4; ++kk) {
            wmma::fragment<wmma::matrix_a, 16, 16, 8, wmma::precision::tf32, wmma::row_major> af;
            wmma::fragment<wmma::matrix_b, 16, 16, 8, wmma::precision::tf32, wmma::row_major> bf;
            wmma::load_matrix_sync(af, Ab + (wr * 16) * 36 + kk * 8, 36);
            wmma::load_matrix_sync(bf, Bb + (kk * 8) * 36 + wc * 16, 36);
            wmma::mma_sync(acc, af, bf, acc);
        }
        if (kt + 1 < nk) {
            int nb = buf ^ 1;
            *(float4*)&As[nb * 2304 + ar * 36 + ac]        = a0;
            *(float4*)&As[nb * 2304 + (ar + 32) * 36 + ac] = a1;
            *(float4*)&Bs[nb * 1152 + ar * 36 + ac]        = b0;
        }
        __syncthreads();
    }
}

__device__ __forceinline__ float sigm(float x) { return 1.f / (1.f + expf(-x)); }

__global__ __launch_bounds__(256, 1)
void recur_kernel(const float* __restrict__ enc,
                  const float* __restrict__ wfull,
                  const float* __restrict__ bfull,
                  float* __restrict__ alpha_out)
{
    __shared__ float sbuf[6912];

    const int bi = blockIdx.x;
    const int tid = threadIdx.x;
    const int wid = tid >> 5, lane = tid & 31;

    float* S = g_scratch;
    const float* att_enc = S + OFF_ATT_ENC;
    const float* Wcat    = S + OFF_WCAT;
    const float* bcat    = S + OFF_BCAT;
    const float* Wrec    = S + OFF_WREC;
    const float* ebias   = S + OFF_EBIAS;
    float* sx            = S + OFF_SX;
    float* cbuf          = S + OFF_C;
    float* attdec        = S + OFF_ATTDEC;
    float* hall          = S + OFF_HALL;

    unsigned gen = *(volatile unsigned*)&g_bar_gen;
    const float bf0 = bfull[0];

    for (int t = 0; t < TT; ++t) {
        const int cur = t & 1, nxt = cur ^ 1;
        float* sxc = sx + cur * (64 * 1536);
        float* sxn = sx + nxt * (64 * 1536);

        // ---- P1: attdec = h @ Wcat + bcat (blocks 0..31) ----
        if (bi < 32) {
            wmma::fragment<wmma::accumulator, 16, 16, 8, float> acc;
            wmma::fill_fragment(acc, 0.f);
            tile_gemm_64x32(sxc + 512, 1536, Wcat + bi * 32, 1024, HH, sbuf, acc);
            const int wr = wid & 3, wc = wid >> 2;
            wmma::store_matrix_sync(sbuf + (wr * 16) * 36 + wc * 16, acc, 36, wmma::mem_row_major);
            __syncthreads();
            const int n0 = bi * 32;
            #pragma unroll
            for (int i = 0; i < 8; ++i) {
                int idx = tid + i * 256;
                int r = idx >> 5, c = idx & 31;
                attdec[r * 1024 + n0 + c] = sbuf[r * 36 + c] + bcat[n0 + c];
            }
        }
        grid_sync(gen);

        // ---- P2: attention (blocks 0..63) ----
        if (bi < 64) {
            const int b = bi;
            float* sa = sbuf;
            float* sw = sbuf + 512;
            float* se = sbuf + 1024;
            float* sred = sbuf + 1224;

            for (int i = tid; i < AA; i += 256) {
                sa[i] = attdec[b * 1024 + i];
                sw[i] = wfull[i];
            }
            __syncthreads();

            for (int p = wid; p < PP; p += 8) {
                const float* row = att_enc + (size_t)(b * PP + p) * AA;
                float acc = 0.f;
                #pragma unroll 4
                for (int a = lane; a < AA; a += 32) {
                    float x = row[a] + sa[a];
                    x = x > 0.f ? x : 0.f;
                    acc += x * sw[a];
                }
                #pragma unroll
                for (int o = 16; o; o >>= 1) acc += __shfl_xor_sync(0xffffffffu, acc, o);
                if (lane == 0) se[p] = acc + bf0;
            }
            __syncthreads();

            float v = (tid < PP) ? se[tid] : -1e30f;
            float m = v;
            #pragma unroll
            for (int o = 16; o; o >>= 1) m = fmaxf(m, __shfl_xor_sync(0xffffffffu, m, o));
            if (lane == 0) sred[wid] = m;
            __syncthreads();
            if (wid == 0) {
                float mm = (lane < 8) ? sred[lane] : -1e30f;
                #pragma unroll
                for (int o = 16; o; o >>= 1) mm = fmaxf(mm, __shfl_xor_sync(0xffffffffu, mm, o));
                if (lane == 0) sred[0] = mm;
            }
            __syncthreads();
            float mx = sred[0];
            __syncthreads();

            float ex = (tid < PP) ? expf(v - mx) : 0.f;
            float s = ex;
            #pragma unroll
            for (int o = 16; o; o >>= 1) s += __shfl_xor_sync(0xffffffffu, s, o);
            if (lane == 0) sred[wid] = s;
            __syncthreads();
            if (wid == 0) {
                float ss = (lane < 8) ? sred[lane] : 0.f;
                #pragma unroll
                for (int o = 16; o; o >>= 1) ss += __shfl_xor_sync(0xffffffffu, ss, o);
                if (lane == 0) sred[0] = ss;
            }
            __syncthreads();
            float inv = 1.f / sred[0];

            if (tid < PP) {
                float al = ex * inv;
                se[tid] = al;
                alpha_out[((size_t)b * TT + t) * PP + tid] = al;
            }
            __syncthreads();

            for (int e = tid; e < ENC; e += 256) {
                const float* col = enc + (size_t)(b * PP) * ENC + e;
                float acc = 0.f;
                #pragma unroll 8
                for (int p = 0; p < PP; ++p) acc += se[p] * col[(size_t)p * ENC];
                float fb = attdec[b * 1024 + 512 + e];
                sxc[b * 1536 + e] = tf32r(sigm(fb) * acc);
            }
        }
        grid_sync(gen);

        // ---- P3: gates + fused LSTM (all 128 blocks) ----
        {
            wmma::fragment<wmma::accumulator, 16, 16, 8, float> acc;
            wmma::fill_fragment(acc, 0.f);
            const int n0 = bi * 32;
            tile_gemm_64x32(sxc, 1536, Wrec + n0, 4096, ENC + HH, sbuf, acc);
            const int wr = wid & 3, wc = wid >> 2;
            wmma::store_matrix_sync(sbuf + (wr * 16) * 36 + wc * 16, acc, 36, wmma::mem_row_major);
            __syncthreads();

            #pragma unroll
            for (int i = 0; i < 2; ++i) {
                int p = tid + i * 256;
                int b = p >> 3, jj = p & 7;
                int j = bi * 8 + jj;
                float4 g = *(float4*)&sbuf[b * 36 + jj * 4];
                float4 e = *(const float4*)&ebias[((size_t)t * BB + b) * 4096 + n0 + jj * 4];
                float gi = g.x + e.x, gf = g.y + e.y, gg = g.z + e.z, go = g.w + e.w;
                float co = cbuf[b * 1024 + j];
                float cn = sigm(gf) * co + sigm(gi) * tanhf(gg);
                float h  = sigm(go) * tanhf(cn);
                float hr = tf32r(h);
                cbuf[b * 1024 + j] = cn;
                sxn[b * 1536 + 512 + j] = hr;
                hall[((size_t)t * BB + b) * 1024 + j] = hr;
            }
        }
        grid_sync(gen);
    }
}

// ---------------- launch ----------------
extern "C" void kernel_launch(void* const* d_in, const int* in_sizes, int n_in,
                              void* d_out, int out_size)
{
    const float* enc       = (const float*)d_in[0];
    const int*   caps      = (const int*)  d_in[1];
    const float* W_enc_att = (const float*)d_in[3];
    const float* b_enc_att = (const float*)d_in[4];
    const float* W_dec_att = (const float*)d_in[5];
    const float* b_dec_att = (const float*)d_in[6];
    const float* W_full    = (const float*)d_in[7];
    const float* b_full    = (const float*)d_in[8];
    const float* emb       = (const float*)d_in[9];
    const float* W_ih      = (const float*)d_in[10];
    const float* b_ih      = (const float*)d_in[11];
    const float* W_hh      = (const float*)d_in[12];
    const float* b_hh      = (const float*)d_in[13];
    const float* W_init_h  = (const float*)d_in[14];
    const float* b_init_h  = (const float*)d_in[15];
    const float* W_init_c  = (const float*)d_in[16];
    const float* b_init_c  = (const float*)d_in[17];
    const float* W_fbeta   = (const float*)d_in[18];
    const float* b_fbeta   = (const float*)d_in[19];
    const float* W_fc      = (const float*)d_in[20];
    const float* b_fc      = (const float*)d_in[21];

    float* out = (float*)d_out;
    float* alpha_out = out + (size_t)BB * TT * VV;

    void* sp = nullptr;
    cudaGetSymbolAddress(&sp, g_scratch);
    float* S = (float*)sp;

    cudaFuncSetAttribute(gemm2<0, 0, 0>, cudaFuncAttributeMaxDynamicSharedMemorySize, G2_SMEM_BYTES);
    cudaFuncSetAttribute(gemm2<0, 0, 1>, cudaFuncAttributeMaxDynamicSharedMemorySize, G2_SMEM_BYTES);
    cudaFuncSetAttribute(gemm2<2, 0, 0>, cudaFuncAttributeMaxDynamicSharedMemorySize, G2_SMEM_BYTES);
    cudaFuncSetAttribute(gemm2<0, 1, 0>, cudaFuncAttributeMaxDynamicSharedMemorySize, G2_SMEM_BYTES);

    // 1. pack / permute / pre-round weights (+ rounded copies of big operands)
    prep_kernel<<<2048, 256>>>(W_dec_att, W_fbeta, b_dec_att, b_fbeta, W_ih, W_hh, b_ih, b_hh,
                               enc, emb, W_fc, W_enc_att, W_init_h, W_init_c);

    // 2. mean over P (rounded)
    mean_kernel<<<BB, 256>>>(enc);

    // 3. h0 (rounded, into sx h-slot) ; c0 (fp32)
    gemm2<0, 0, 1><<<dim3(8, 1), 128, G2_SMEM_BYTES>>>(
        S + OFF_MEAN, ENC, nullptr, nullptr, S + OFF_WIH0, HH,
        S + OFF_SX + 512, 1536, b_init_h, BB, HH, ENC);
    gemm2<0, 0, 0><<<dim3(8, 1), 128, G2_SMEM_BYTES>>>(
        S + OFF_MEAN, ENC, nullptr, nullptr, S + OFF_WIC0, HH,
        S + OFF_C, HH, b_init_c, BB, HH, ENC);

    // 4. att_enc = enc_r @ W_enc_att_r + b_enc_att
    gemm2<0, 0, 0><<<dim3(4, 98), 128, G2_SMEM_BYTES>>>(
        S + OFF_ENC_R, ENC, nullptr, nullptr, S + OFF_WEA_R, AA,
        S + OFF_ATT_ENC, AA, b_enc_att, BB * PP, AA, ENC);

    // 5. ebias = emb_r[caps] @ Wih_perm + brec (permuted cols)
    gemm2<2, 0, 0><<<dim3(32, 12), 128, G2_SMEM_BYTES>>>(
        nullptr, 0, S + OFF_EMB_R, caps, S + OFF_WIH, 4096,
        S + OFF_EBIAS, 4096, S + OFF_BREC, TT * BB, 4096, EE);

    // 6. persistent 24-step recurrence
    recur_kernel<<<NBLK, 256>>>(enc, W_full, b_full, alpha_out);

    // 7. predictions = hall @ W_fc_r + b_fc (remapped to (B,T,V))
    gemm2<0, 1, 0><<<dim3(157, 12), 128, G2_SMEM_BYTES>>>(
        S + OFF_HALL, HH, nullptr, nullptr, S + OFF_WFC_R, VV,
        out, VV, b_fc, TT * BB, VV, HH);
}

// round 7
// speedup vs baseline: 1.2955x; 1.0724x over previous
#include <cuda_runtime.h>
#include <cuda_bf16.h>
#include <mma.h>
#include <math.h>
#include <cstdint>

using namespace nvcuda;

// ---------------- problem constants ----------------
#define BB    64
#define PP    196
#define ENC   512
#define EE    1024
#define HH    1024
#define AA    512
#define VV    20000
#define LL    25
#define TT    24

// ---------------- scratch layout (floats) ----------------
#define OFF_ATT_ENC  0u            // 12544*512
#define OFF_EBIAS    6422528u      // 1536*4096
#define OFF_WREC     12713984u     // 1536*4096 (tf32, col-permuted)
#define OFF_WIH      19005440u     // 1024*4096 (tf32, col-permuted)
#define OFF_WCAT     23199744u     // 1024*1024 (tf32)
#define OFF_BCAT     24248320u     // 1024
#define OFF_BREC     24249344u     // 4096
#define OFF_MEAN     24253440u     // 64*512 (tf32)
#define OFF_SX       24286208u     // 2 * 64*1536 (tf32 [gc | h])
#define OFF_C        24482816u     // 64*1024 (fp32)
#define OFF_ATTDEC   24548352u     // 64*1024 (fp32)
#define OFF_HALL     24613888u     // 1536*1024 (tf32)
#define OFF_ENC_R    26186752u     // 12544*512 tf32 enc
#define OFF_EMB_R    32609280u     // 20000*1024 tf32 emb
#define OFF_WFC_R    53089280u     // 1024*20000 tf32 W_fc
#define OFF_WEA_R    73569280u     // 512*512
#define OFF_W0       73831424u     // 512*2048 = [W_init_h | W_init_c] tf32
#define OFF_B0       74880000u     // 2048
#define SCRATCH_TOTAL 74882048u

__device__ __align__(256) float g_scratch[SCRATCH_TOTAL];

__device__ unsigned g_bar_count = 0;
__device__ unsigned g_bar_gen   = 0;

__device__ __forceinline__ float tf32r(float x) { return wmma::__float_to_tf32(x); }

__device__ __forceinline__ void cp16(unsigned int dst, const float* src, int pred)
{
    asm volatile(
        "{\n\t.reg .pred p;\n\t"
        "setp.ne.b32 p, %2, 0;\n\t"
        "@p cp.async.cg.shared.global [%0], [%1], 16;\n\t}\n"
        :: "r"(dst), "l"(src), "r"(pred));
}

// ---------------- prep: pack / permute / pre-round weights ----------------
__global__ void prep_kernel(const float* __restrict__ Wdec, const float* __restrict__ Wfb,
                            const float* __restrict__ bdec, const float* __restrict__ bfb,
                            const float* __restrict__ Wih,  const float* __restrict__ Whh,
                            const float* __restrict__ bih,  const float* __restrict__ bhh,
                            const float* __restrict__ enc,  const float* __restrict__ emb,
                            const float* __restrict__ Wfc,  const float* __restrict__ Wea,
                            const float* __restrict__ Wih0, const float* __restrict__ Wic0,
                            const float* __restrict__ bih0, const float* __restrict__ bic0)
{
    float* Wcat = g_scratch + OFF_WCAT;
    float* bcat = g_scratch + OFF_BCAT;
    float* Wrec = g_scratch + OFF_WREC;
    float* Wihp = g_scratch + OFF_WIH;
    float* brec = g_scratch + OFF_BREC;
    float* encr = g_scratch + OFF_ENC_R;
    float* embr = g_scratch + OFF_EMB_R;
    float* wfcr = g_scratch + OFF_WFC_R;
    float* wear = g_scratch + OFF_WEA_R;
    float* w0   = g_scratch + OFF_W0;
    float* b0   = g_scratch + OFF_B0;

    int i = blockIdx.x * blockDim.x + threadIdx.x;
    int stride = gridDim.x * blockDim.x;

    for (int idx = i; idx < 1024 * 1024; idx += stride) {
        int k = idx >> 10, c = idx & 1023;
        Wcat[idx] = tf32r((c < 512) ? Wdec[k * 512 + c] : Wfb[k * 512 + (c - 512)]);
    }
    for (int idx = i; idx < 1024; idx += stride)
        bcat[idx] = (idx < 512) ? bdec[idx] : bfb[idx - 512];

    for (int idx = i; idx < 1536 * 4096; idx += stride) {
        int r = idx >> 12, cp = idx & 4095;
        int j = cp >> 2, q = cp & 3;
        int oc = q * 1024 + j;
        Wrec[idx] = tf32r((r < 512) ? Wih[(size_t)(1024 + r) * 4096 + oc]
                                    : Whh[(size_t)(r - 512) * 4096 + oc]);
    }
    for (int idx = i; idx < 1024 * 4096; idx += stride) {
        int r = idx >> 12, cp = idx & 4095;
        int j = cp >> 2, q = cp & 3;
        Wihp[idx] = tf32r(Wih[(size_t)r * 4096 + q * 1024 + j]);
    }
    for (int idx = i; idx < 4096; idx += stride) {
        int j = idx >> 2, q = idx & 3;
        brec[idx] = bih[q * 1024 + j] + bhh[q * 1024 + j];
    }
    for (int idx = i; idx < BB * PP * ENC; idx += stride) encr[idx] = tf32r(enc[idx]);
    for (int idx = i; idx < VV * EE;       idx += stride) embr[idx] = tf32r(emb[idx]);
    for (int idx = i; idx < HH * VV;       idx += stride) wfcr[idx] = tf32r(Wfc[idx]);
    for (int idx = i; idx < ENC * AA;      idx += stride) wear[idx] = tf32r(Wea[idx]);
    for (int idx = i; idx < 512 * 2048;    idx += stride) {
        int r = idx >> 11, c = idx & 2047;
        w0[idx] = tf32r((c < 1024) ? Wih0[r * 1024 + c] : Wic0[r * 1024 + (c - 1024)]);
    }
    for (int idx = i; idx < 2048; idx += stride)
        b0[idx] = (idx < 1024) ? bih0[idx] : bic0[idx - 1024];
}

// ---------------- mean over P (tf32-rounded output) ----------------
__global__ void mean_kernel(const float* __restrict__ enc)
{
    int b = blockIdx.x;
    float* mean = g_scratch + OFF_MEAN;
    for (int e = threadIdx.x; e < ENC; e += blockDim.x) {
        float s = 0.f;
        const float* base = enc + (size_t)(b * PP) * ENC + e;
        #pragma unroll 4
        for (int p = 0; p < PP; ++p) s += base[(size_t)p * ENC];
        mean[b * ENC + e] = tf32r(s * (1.f / (float)PP));
    }
}

// ====== gemm2: 128x128 tile, 256 thr / 8 warps (32x64), cp.async 3-stage ======
// AMODE 0: plain A (row-clamped);  2: rows gathered from emb_r via caps
// CMODE 0: plain C;  1: preds remap m=t*64+b -> C[(b*24+t)][n];
//       2: init split: n<1024 -> sx h-slot (tf32), else -> cbuf (fp32)
// CROUND: round stored value to tf32
#define NS   3
#define G2BM 128
#define G2BN 128
#define G2BK 32
#define G2ASTR 36
#define G2BSTR 132
#define G2ASZ (G2BM * G2ASTR)     // 4608
#define G2BSZ (G2BK * G2BSTR)     // 4224
#define G2STG (G2ASZ + G2BSZ)     // 8832 floats
#define G2_SMEM_BYTES (NS * G2STG * 4)   // 105984

template<int AMODE, int CMODE, int CROUND>
__global__ __launch_bounds__(256, 2)
void gemm2(const float* __restrict__ A, int lda,
           const float* __restrict__ emb, const int* __restrict__ caps,
           const float* __restrict__ B, int ldb,
           float* __restrict__ C, int ldc,
           const float* __restrict__ bias,
           int M, int N, int K)
{
    extern __shared__ float dyn[];
    __shared__ int scap[G2BM];

    const int tid = threadIdx.x;
    const int n0 = blockIdx.x * G2BN;
    const int m0 = blockIdx.y * G2BM;

    if (AMODE == 2) {
        if (tid < G2BM) {
            int m = m0 + tid;
            int tt = m >> 6, bb = m & 63;
            scap[tid] = caps[bb * LL + tt];
        }
        __syncthreads();
    }

    // copy chunks: 4 float4 for A (q = tid + i*256), 4 for B
    const float* arow[4];
    const float* brow[4];
    int bval[4];
    #pragma unroll
    for (int i = 0; i < 4; ++i) {
        int q = tid + i * 256;
        int r = q >> 3;                    // 0..127
        if (AMODE == 0) {
            int gr = m0 + r; if (gr >= M) gr = M - 1;
            arow[i] = A + (size_t)gr * lda;
        } else {
            arow[i] = emb + (size_t)scap[r] * EE;
        }
        int br = q >> 5;                   // 0..31
        int bcn = (q & 31) * 4;            // 0..124
        brow[i] = B + (size_t)br * ldb + n0 + bcn;
        bval[i] = (n0 + bcn) < N;
    }
    const unsigned int sbase = (unsigned int)__cvta_generic_to_shared(dyn);

    auto load_stage = [&](int kt, int s) {
        const unsigned int so = sbase + (unsigned int)(s * G2STG) * 4u;
        const int k0 = kt * G2BK;
        #pragma unroll
        for (int i = 0; i < 4; ++i) {
            int q = tid + i * 256;
            int r = q >> 3, c = (q & 7) * 4;
            cp16(so + (unsigned int)(r * G2ASTR + c) * 4u, arow[i] + k0 + c, 1);
        }
        #pragma unroll
        for (int i = 0; i < 4; ++i) {
            int q = tid + i * 256;
            int br = q >> 5, bcn = (q & 31) * 4;
            cp16(so + (unsigned int)(G2ASZ + br * G2BSTR + bcn) * 4u,
                 brow[i] + (size_t)k0 * ldb, bval[i]);
        }
        asm volatile("cp.async.commit_group;\n" ::: "memory");
    };

    const int nk = K / G2BK;
    #pragma unroll
    for (int s = 0; s < NS - 1; ++s) load_stage(s, s);

    const int wid = tid >> 5;
    const int wr = wid & 3;       // 4 m-chunks of 32
    const int wc = wid >> 2;      // 2 n-chunks of 64

    wmma::fragment<wmma::accumulator, 16, 16, 8, float> acc[2][4];
    #pragma unroll
    for (int i = 0; i < 2; ++i)
        #pragma unroll
        for (int j = 0; j < 4; ++j) wmma::fill_fragment(acc[i][j], 0.f);

    for (int kt = 0; kt < nk; ++kt) {
        asm volatile("cp.async.wait_group 1;\n" ::: "memory");
        __syncthreads();

        if (kt + NS - 1 < nk) load_stage(kt + NS - 1, (kt + NS - 1) % NS);
        else asm volatile("cp.async.commit_group;\n" ::: "memory");

        const float* Ab = dyn + (kt % NS) * G2STG;
        const float* Bb = Ab + G2ASZ;
        #pragma unroll
        for (int ks = 0; ks < 4; ++ks) {
            wmma::fragment<wmma::matrix_a, 16, 16, 8, wmma::precision::tf32, wmma::row_major> af[2];
            wmma::fragment<wmma::matrix_b, 16, 16, 8, wmma::precision::tf32, wmma::row_major> bf[4];
            #pragma unroll
            for (int i = 0; i < 2; ++i)
                wmma::load_matrix_sync(af[i], Ab + (wr * 32 + i * 16) * G2ASTR + ks * 8, G2ASTR);
            #pragma unroll
            for (int j = 0; j < 4; ++j)
                wmma::load_matrix_sync(bf[j], Bb + (ks * 8) * G2BSTR + wc * 64 + j * 16, G2BSTR);
            #pragma unroll
            for (int i = 0; i < 2; ++i)
                #pragma unroll
                for (int j = 0; j < 4; ++j)
                    wmma::mma_sync(acc[i][j], af[i], bf[j], acc[i][j]);
        }
    }
    asm volatile("cp.async.wait_group 0;\n" ::: "memory");
    __syncthreads();

    // epilogue: 4 chunks of 32 rows staged through smem
    float* Cs = dyn;   // 32 x G2BSTR
    for (int chunk = 0; chunk < 4; ++chunk) {
        if (wr == chunk) {
            #pragma unroll
            for (int i = 0; i < 2; ++i)
                #pragma unroll
                for (int j = 0; j < 4; ++j)
                    wmma::store_matrix_sync(Cs + (i * 16) * G2BSTR + wc * 64 + j * 16,
                                            acc[i][j], G2BSTR, wmma::mem_row_major);
        }
        __syncthreads();
        #pragma unroll
        for (int it = 0; it < 16; ++it) {
            int idx = tid + it * 256;
            int r = idx >> 7, cn = idx & 127;
            int m = m0 + chunk * 32 + r;
            int n = n0 + cn;
            if (m < M && n < N) {
                float v = Cs[r * G2BSTR + cn] + bias[n];
                if (CROUND) v = tf32r(v);
                if (CMODE == 0) {
                    C[(size_t)m * ldc + n] = v;
                } else if (CMODE == 1) {
                    int bb = m & 63, tt = m >> 6;
                    C[((size_t)bb * TT + tt) * ldc + n] = v;
                } else {
                    if (n < 1024) g_scratch[OFF_SX + 512u + (unsigned)m * 1536u + (unsigned)n] = tf32r(v);
                    else          g_scratch[OFF_C + (unsigned)m * 1024u + (unsigned)(n - 1024)] = v;
                }
            }
        }
        __syncthreads();
    }
}

// ================= persistent recurrence kernel =================
#define NBLK 128
#define TGSTG 3456            // (64+32)*36 floats per stage
#define SBUF_FLOATS (3 * TGSTG)   // 10368

__device__ __forceinline__ void grid_sync(unsigned& gen)
{
    __syncthreads();
    if (threadIdx.x == 0) {
        __threadfence();
        unsigned arrived = atomicAdd(&g_bar_count, 1u);
        if (arrived == (unsigned)(NBLK - 1)) {
            g_bar_count = 0;
            __threadfence();
            atomicAdd(&g_bar_gen, 1u);
        } else {
            while (*(volatile unsigned*)&g_bar_gen == gen) __nanosleep(64);
            __threadfence();
        }
    }
    gen++;
    __syncthreads();
}

// 64x32 wmma gemm, GBK=32, cp.async 3-stage.
__device__ __forceinline__ void tile_gemm_64x32(
    const float* __restrict__ A, int lda,
    const float* __restrict__ B, int ldb, int K,
    float* sbuf,
    wmma::fragment<wmma::accumulator, 16, 16, 8, float>& acc)
{
    const int tid = threadIdx.x;
    const int wid = tid >> 5, wr = wid & 3, wc = wid >> 2;
    const unsigned int sb = (unsigned int)__cvta_generic_to_shared(sbuf);
    const int nk = K >> 5;

    auto load_stage = [&](int kt, int s) {
        const unsigned int so = sb + (unsigned int)(s * TGSTG) * 4u;
        const int k0 = kt * 32;
        #pragma unroll
        for (int i = 0; i < 2; ++i) {
            int q = tid + i * 256;
            int r = q >> 3, c = (q & 7) * 4;   // r 0..63
            cp16(so + (unsigned int)(r * 36 + c) * 4u, A + (size_t)r * lda + k0 + c, 1);
        }
        {
            int r = tid >> 3, c = (tid & 7) * 4;  // r 0..31
            cp16(so + (unsigned int)(2304 + r * 36 + c) * 4u, B + (size_t)(k0 + r) * ldb + c, 1);
        }
        asm volatile("cp.async.commit_group;\n" ::: "memory");
    };

    load_stage(0, 0);
    load_stage(1, 1);

    for (int kt = 0; kt < nk; ++kt) {
        asm volatile("cp.async.wait_group 1;\n" ::: "memory");
        __syncthreads();
        if (kt + 2 < nk) load_stage(kt + 2, (kt + 2) % 3);
        else asm volatile("cp.async.commit_group;\n" ::: "memory");

        const float* Ab = sbuf + (kt % 3) * TGSTG;
        const float* Bb = Ab + 2304;
        #pragma unroll
        for (int kk = 0; kk < 4; ++kk) {
            wmma::fragment<wmma::matrix_a, 16, 16, 8, wmma::precision::tf32, wmma::row_major> af;
            wmma::fragment<wmma::matrix_b, 16, 16, 8, wmma::precision::tf32, wmma::row_major> bf;
            wmma::load_matrix_sync(af, Ab + (wr * 16) * 36 + kk * 8, 36);
            wmma::load_matrix_sync(bf, Bb + (kk * 8) * 36 + wc * 16, 36);
            wmma::mma_sync(acc, af, bf, acc);
        }
    }
    asm volatile("cp.async.wait_group 0;\n" ::: "memory");
    __syncthreads();
}

__device__ __forceinline__ float sigm(float x) { return 1.f / (1.f + expf(-x)); }

__global__ __launch_bounds__(256, 1)
void recur_kernel(const float* __restrict__ enc,
                  const float* __restrict__ wfull,
                  const float* __restrict__ bfull,
                  float* __restrict__ alpha_out)
{
    __shared__ float sbuf[SBUF_FLOATS];

    const int bi = blockIdx.x;
    const int tid = threadIdx.x;
    const int wid = tid >> 5, lane = tid & 31;

    float* S = g_scratch;
    const float* att_enc = S + OFF_ATT_ENC;
    const float* Wcat    = S + OFF_WCAT;
    const float* bcat    = S + OFF_BCAT;
    const float* Wrec    = S + OFF_WREC;
    const float* ebias   = S + OFF_EBIAS;
    float* sx            = S + OFF_SX;
    float* cbuf          = S + OFF_C;
    float* attdec        = S + OFF_ATTDEC;
    float* hall          = S + OFF_HALL;

    unsigned gen = *(volatile unsigned*)&g_bar_gen;
    const float bf0 = bfull[0];

    for (int t = 0; t < TT; ++t) {
        const int cur = t & 1, nxt = cur ^ 1;
        float* sxc = sx + cur * (64 * 1536);
        float* sxn = sx + nxt * (64 * 1536);

        // ---- P1: attdec = h @ Wcat + bcat (blocks 0..31) ----
        if (bi < 32) {
            wmma::fragment<wmma::accumulator, 16, 16, 8, float> acc;
            wmma::fill_fragment(acc, 0.f);
            tile_gemm_64x32(sxc + 512, 1536, Wcat + bi * 32, 1024, HH, sbuf, acc);
            const int wr = wid & 3, wc = wid >> 2;
            wmma::store_matrix_sync(sbuf + (wr * 16) * 36 + wc * 16, acc, 36, wmma::mem_row_major);
            __syncthreads();
            const int n0 = bi * 32;
            #pragma unroll
            for (int i = 0; i < 8; ++i) {
                int idx = tid + i * 256;
                int r = idx >> 5, c = idx & 31;
                attdec[r * 1024 + n0 + c] = sbuf[r * 36 + c] + bcat[n0 + c];
            }
        }
        grid_sync(gen);

        // ---- P2: attention (blocks 0..63) ----
        if (bi < 64) {
            const int b = bi;
            float* sa = sbuf;
            float* sw = sbuf + 512;
            float* se = sbuf + 1024;
            float* sred = sbuf + 1224;

            for (int i = tid; i < AA; i += 256) {
                sa[i] = attdec[b * 1024 + i];
                sw[i] = wfull[i];
            }
            __syncthreads();

            for (int p = wid; p < PP; p += 8) {
                const float* row = att_enc + (size_t)(b * PP + p) * AA;
                float acc = 0.f;
                #pragma unroll 4
                for (int a = lane; a < AA; a += 32) {
                    float x = row[a] + sa[a];
                    x = x > 0.f ? x : 0.f;
                    acc += x * sw[a];
                }
                #pragma unroll
                for (int o = 16; o; o >>= 1) acc += __shfl_xor_sync(0xffffffffu, acc, o);
                if (lane == 0) se[p] = acc + bf0;
            }
            __syncthreads();

            float v = (tid < PP) ? se[tid] : -1e30f;
            float m = v;
            #pragma unroll
            for (int o = 16; o; o >>= 1) m = fmaxf(m, __shfl_xor_sync(0xffffffffu, m, o));
            if (lane == 0) sred[wid] = m;
            __syncthreads();
            if (wid == 0) {
                float mm = (lane < 8) ? sred[lane] : -1e30f;
                #pragma unroll
                for (int o = 16; o; o >>= 1) mm = fmaxf(mm, __shfl_xor_sync(0xffffffffu, mm, o));
                if (lane == 0) sred[0] = mm;
            }
            __syncthreads();
            float mx = sred[0];
            __syncthreads();

            float ex = (tid < PP) ? expf(v - mx) : 0.f;
            float s = ex;
            #pragma unroll
            for (int o = 16; o; o >>= 1) s += __shfl_xor_sync(0xffffffffu, s, o);
            if (lane == 0) sred[wid] = s;
            __syncthreads();
            if (wid == 0) {
                float ss = (lane < 8) ? sred[lane] : 0.f;
                #pragma unroll
                for (int o = 16; o; o >>= 1) ss += __shfl_xor_sync(0xffffffffu, ss, o);
                if (lane == 0) sred[0] = ss;
            }
            __syncthreads();
            float inv = 1.f / sred[0];

            if (tid < PP) {
                float al = ex * inv;
                se[tid] = al;
                alpha_out[((size_t)b * TT + t) * PP + tid] = al;
            }
            __syncthreads();

            for (int e = tid; e < ENC; e += 256) {
                const float* col = enc + (size_t)(b * PP) * ENC + e;
                float acc = 0.f;
                #pragma unroll 8
                for (int p = 0; p < PP; ++p) acc += se[p] * col[(size_t)p * ENC];
                float fb = attdec[b * 1024 + 512 + e];
                sxc[b * 1536 + e] = tf32r(sigm(fb) * acc);
            }
        }
        grid_sync(gen);

        // ---- P3: gates + fused LSTM (all 128 blocks) ----
        {
            wmma::fragment<wmma::accumulator, 16, 16, 8, float> acc;
            wmma::fill_fragment(acc, 0.f);
            const int n0 = bi * 32;
            tile_gemm_64x32(sxc, 1536, Wrec + n0, 4096, ENC + HH, sbuf, acc);
            const int wr = wid & 3, wc = wid >> 2;
            wmma::store_matrix_sync(sbuf + (wr * 16) * 36 + wc * 16, acc, 36, wmma::mem_row_major);
            __syncthreads();

            #pragma unroll
            for (int i = 0; i < 2; ++i) {
                int p = tid + i * 256;
                int b = p >> 3, jj = p & 7;
                int j = bi * 8 + jj;
                float4 g = *(float4*)&sbuf[b * 36 + jj * 4];
                float4 e = *(const float4*)&ebias[((size_t)t * BB + b) * 4096 + n0 + jj * 4];
                float gi = g.x + e.x, gf = g.y + e.y, gg = g.z + e.z, go = g.w + e.w;
                float co = cbuf[b * 1024 + j];
                float cn = sigm(gf) * co + sigm(gi) * tanhf(gg);
                float h  = sigm(go) * tanhf(cn);
                float hr = tf32r(h);
                cbuf[b * 1024 + j] = cn;
                sxn[b * 1536 + 512 + j] = hr;
                hall[((size_t)t * BB + b) * 1024 + j] = hr;
            }
        }
        grid_sync(gen);
    }
}

// ---------------- launch ----------------
extern "C" void kernel_launch(void* const* d_in, const int* in_sizes, int n_in,
                              void* d_out, int out_size)
{
    const float* enc       = (const float*)d_in[0];
    const int*   caps      = (const int*)  d_in[1];
    const float* W_enc_att = (const float*)d_in[3];
    const float* b_enc_att = (const float*)d_in[4];
    const float* W_dec_att = (const float*)d_in[5];
    const float* b_dec_att = (const float*)d_in[6];
    const float* W_full    = (const float*)d_in[7];
    const float* b_full    = (const float*)d_in[8];
    const float* emb       = (const float*)d_in[9];
    const float* W_ih      = (const float*)d_in[10];
    const float* b_ih      = (const float*)d_in[11];
    const float* W_hh      = (const float*)d_in[12];
    const float* b_hh      = (const float*)d_in[13];
    const float* W_init_h  = (const float*)d_in[14];
    const float* b_init_h  = (const float*)d_in[15];
    const float* W_init_c  = (const float*)d_in[16];
    const float* b_init_c  = (const float*)d_in[17];
    const float* W_fbeta   = (const float*)d_in[18];
    const float* b_fbeta   = (const float*)d_in[19];
    const float* W_fc      = (const float*)d_in[20];
    const float* b_fc      = (const float*)d_in[21];

    float* out = (float*)d_out;
    float* alpha_out = out + (size_t)BB * TT * VV;

    void* sp = nullptr;
    cudaGetSymbolAddress(&sp, g_scratch);
    float* S = (float*)sp;

    cudaFuncSetAttribute(gemm2<0, 0, 0>, cudaFuncAttributeMaxDynamicSharedMemorySize, G2_SMEM_BYTES);
    cudaFuncSetAttribute(gemm2<0, 2, 0>, cudaFuncAttributeMaxDynamicSharedMemorySize, G2_SMEM_BYTES);
    cudaFuncSetAttribute(gemm2<2, 0, 0>, cudaFuncAttributeMaxDynamicSharedMemorySize, G2_SMEM_BYTES);
    cudaFuncSetAttribute(gemm2<0, 1, 0>, cudaFuncAttributeMaxDynamicSharedMemorySize, G2_SMEM_BYTES);

    // 1. pack / permute / pre-round weights
    prep_kernel<<<2048, 256>>>(W_dec_att, W_fbeta, b_dec_att, b_fbeta, W_ih, W_hh, b_ih, b_hh,
                               enc, emb, W_fc, W_enc_att, W_init_h, W_init_c,
                               b_init_h, b_init_c);

    // 2. mean over P (rounded)
    mean_kernel<<<BB, 256>>>(enc);

    // 3. [h0 | c0] = mean @ W0 + b0 (single launch, split epilogue)
    gemm2<0, 2, 0><<<dim3(16, 1), 256, G2_SMEM_BYTES>>>(
        S + OFF_MEAN, ENC, nullptr, nullptr, S + OFF_W0, 2048,
        S, 0, S + OFF_B0, BB, 2048, ENC);

    // 4. att_enc = enc_r @ W_enc_att_r + b_enc_att
    gemm2<0, 0, 0><<<dim3(4, 98), 256, G2_SMEM_BYTES>>>(
        S + OFF_ENC_R, ENC, nullptr, nullptr, S + OFF_WEA_R, AA,
        S + OFF_ATT_ENC, AA, b_enc_att, BB * PP, AA, ENC);

    // 5. ebias = emb_r[caps] @ Wih_perm + brec (permuted cols)
    gemm2<2, 0, 0><<<dim3(32, 12), 256, G2_SMEM_BYTES>>>(
        nullptr, 0, S + OFF_EMB_R, caps, S + OFF_WIH, 4096,
        S + OFF_EBIAS, 4096, S + OFF_BREC, TT * BB, 4096, EE);

    // 6. persistent 24-step recurrence
    recur_kernel<<<NBLK, 256>>>(enc, W_full, b_full, alpha_out);

    // 7. predictions = hall @ W_fc_r + b_fc (remapped to (B,T,V))
    gemm2<0, 1, 0><<<dim3(157, 12), 256, G2_SMEM_BYTES>>>(
        S + OFF_HALL, HH, nullptr, nullptr, S + OFF_WFC_R, VV,
        out, VV, b_fc, TT * BB, VV, HH);
}

// round 9
// speedup vs baseline: 1.5208x; 1.1739x over previous
#include <cuda_runtime.h>
#include <cuda_bf16.h>
#include <mma.h>
#include <math.h>
#include <cstdint>

using namespace nvcuda;

// ---------------- problem constants ----------------
#define BB    64
#define PP    196
#define ENC   512
#define EE    1024
#define HH    1024
#define AA    512
#define VV    20000
#define LL    25
#define TT    24

// ---------------- scratch layout (floats) ----------------
#define OFF_ATT_ENC  0u            // 12544*512
#define OFF_EBIAS    6422528u      // 1536*4096
#define OFF_WREC     12713984u     // 1536*4096 (tf32, col-permuted)
#define OFF_WIH      19005440u     // 1024*4096 (tf32, col-permuted)
#define OFF_WCAT     23199744u     // 1024*1024 (tf32)
#define OFF_BCAT     24248320u     // 1024
#define OFF_BREC     24249344u     // 4096
#define OFF_MEAN     24253440u     // 64*512 (tf32)
#define OFF_SX       24286208u     // 2 * 64*1536 (tf32 [gc | h])
#define OFF_C        24482816u     // 64*1024 (fp32)
#define OFF_ATTDEC   24548352u     // 64*1024 (fp32)
#define OFF_HALL     24613888u     // 1536*1024 (tf32)
#define OFF_ENC_R    26186752u     // 12544*512 tf32 enc
#define OFF_EMBG     32609280u     // 1536*1024 gathered+rounded embeddings
#define OFF_WFC_R    53089280u     // 1024*20000 tf32 W_fc
#define OFF_WEA_R    73569280u     // 512*512
#define OFF_W0       73831424u     // 512*2048 = [W_init_h | W_init_c] tf32
#define OFF_B0       74880000u     // 2048
#define SCRATCH_TOTAL 74882048u

__device__ __align__(256) float g_scratch[SCRATCH_TOTAL];

__device__ unsigned g_bar_count = 0;
__device__ unsigned g_bar_gen   = 0;

__device__ __forceinline__ float tf32r(float x) { return wmma::__float_to_tf32(x); }

__device__ __forceinline__ void cp16(unsigned int dst, const float* src, int pred)
{
    asm volatile(
        "{\n\t.reg .pred p;\n\t"
        "setp.ne.b32 p, %2, 0;\n\t"
        "@p cp.async.cg.shared.global [%0], [%1], 16;\n\t}\n"
        :: "r"(dst), "l"(src), "r"(pred));
}

// ---------------- prep: pack / permute / pre-round weights + mean + emb gather ----------------
__global__ void prep_kernel(const float* __restrict__ Wdec, const float* __restrict__ Wfb,
                            const float* __restrict__ bdec, const float* __restrict__ bfb,
                            const float* __restrict__ Wih,  const float* __restrict__ Whh,
                            const float* __restrict__ bih,  const float* __restrict__ bhh,
                            const float* __restrict__ enc,  const float* __restrict__ emb,
                            const float* __restrict__ Wfc,  const float* __restrict__ Wea,
                            const float* __restrict__ Wih0, const float* __restrict__ Wic0,
                            const float* __restrict__ bih0, const float* __restrict__ bic0,
                            const int*   __restrict__ caps)
{
    float* Wcat = g_scratch + OFF_WCAT;
    float* bcat = g_scratch + OFF_BCAT;
    float* Wrec = g_scratch + OFF_WREC;
    float* Wihp = g_scratch + OFF_WIH;
    float* brec = g_scratch + OFF_BREC;
    float* encr = g_scratch + OFF_ENC_R;
    float* embg = g_scratch + OFF_EMBG;
    float* wfcr = g_scratch + OFF_WFC_R;
    float* wear = g_scratch + OFF_WEA_R;
    float* w0   = g_scratch + OFF_W0;
    float* b0   = g_scratch + OFF_B0;
    float* mean = g_scratch + OFF_MEAN;

    int i = blockIdx.x * blockDim.x + threadIdx.x;
    int stride = gridDim.x * blockDim.x;

    for (int idx = i; idx < 1024 * 1024; idx += stride) {
        int k = idx >> 10, c = idx & 1023;
        Wcat[idx] = tf32r((c < 512) ? Wdec[k * 512 + c] : Wfb[k * 512 + (c - 512)]);
    }
    for (int idx = i; idx < 1024; idx += stride)
        bcat[idx] = (idx < 512) ? bdec[idx] : bfb[idx - 512];

    for (int idx = i; idx < 1536 * 4096; idx += stride) {
        int r = idx >> 12, cp = idx & 4095;
        int j = cp >> 2, q = cp & 3;
        int oc = q * 1024 + j;
        Wrec[idx] = tf32r((r < 512) ? Wih[(size_t)(1024 + r) * 4096 + oc]
                                    : Whh[(size_t)(r - 512) * 4096 + oc]);
    }
    for (int idx = i; idx < 1024 * 4096; idx += stride) {
        int r = idx >> 12, cp = idx & 4095;
        int j = cp >> 2, q = cp & 3;
        Wihp[idx] = tf32r(Wih[(size_t)r * 4096 + q * 1024 + j]);
    }
    for (int idx = i; idx < 4096; idx += stride) {
        int j = idx >> 2, q = idx & 3;
        brec[idx] = bih[q * 1024 + j] + bhh[q * 1024 + j];
    }
    for (int idx = i; idx < BB * PP * ENC; idx += stride) encr[idx] = tf32r(enc[idx]);
    // gather only used embedding rows: row m = t*64+b
    for (int idx = i; idx < TT * BB * EE; idx += stride) {
        int m = idx >> 10, c = idx & 1023;
        int tt = m >> 6, bb = m & 63;
        embg[idx] = tf32r(emb[(size_t)caps[bb * LL + tt] * EE + c]);
    }
    for (int idx = i; idx < HH * VV;  idx += stride) wfcr[idx] = tf32r(Wfc[idx]);
    for (int idx = i; idx < ENC * AA; idx += stride) wear[idx] = tf32r(Wea[idx]);
    for (int idx = i; idx < 512 * 2048; idx += stride) {
        int r = idx >> 11, c = idx & 2047;
        w0[idx] = tf32r((c < 1024) ? Wih0[r * 1024 + c] : Wic0[r * 1024 + (c - 1024)]);
    }
    for (int idx = i; idx < 2048; idx += stride)
        b0[idx] = (idx < 1024) ? bih0[idx] : bic0[idx - 1024];
    // mean over P (tf32-rounded)
    for (int idx = i; idx < BB * ENC; idx += stride) {
        int b = idx >> 9, e = idx & 511;
        float s = 0.f;
        const float* base = enc + (size_t)(b * PP) * ENC + e;
        #pragma unroll 4
        for (int p = 0; p < PP; ++p) s += base[(size_t)p * ENC];
        mean[idx] = tf32r(s * (1.f / (float)PP));
    }
}

// ====== gemm2: 128x128 tile, 256 thr / 8 warps (32x64), cp.async 3-stage ======
// CMODE 0: plain C;  1: preds remap m=t*64+b -> C[(b*24+t)][n];
//       2: init split: n<1024 -> sx h-slot (tf32), else -> cbuf (fp32)
#define NS   3
#define G2BM 128
#define G2BN 128
#define G2BK 32
#define G2ASTR 36
#define G2BSTR 132
#define G2ASZ (G2BM * G2ASTR)
#define G2BSZ (G2BK * G2BSTR)
#define G2STG (G2ASZ + G2BSZ)
#define G2_SMEM_BYTES (NS * G2STG * 4)

template<int CMODE>
__global__ __launch_bounds__(256, 2)
void gemm2(const float* __restrict__ A, int lda,
           const float* __restrict__ B, int ldb,
           float* __restrict__ C, int ldc,
           const float* __restrict__ bias,
           int M, int N, int K)
{
    extern __shared__ float dyn[];

    const int tid = threadIdx.x;
    const int n0 = blockIdx.x * G2BN;
    const int m0 = blockIdx.y * G2BM;

    const float* arow[4];
    const float* brow[4];
    int bval[4];
    #pragma unroll
    for (int i = 0; i < 4; ++i) {
        int q = tid + i * 256;
        int r = q >> 3;
        int gr = m0 + r; if (gr >= M) gr = M - 1;
        arow[i] = A + (size_t)gr * lda;
        int br = q >> 5;
        int bcn = (q & 31) * 4;
        brow[i] = B + (size_t)br * ldb + n0 + bcn;
        bval[i] = (n0 + bcn) < N;
    }
    const unsigned int sbase = (unsigned int)__cvta_generic_to_shared(dyn);

    auto load_stage = [&](int kt, int s) {
        const unsigned int so = sbase + (unsigned int)(s * G2STG) * 4u;
        const int k0 = kt * G2BK;
        #pragma unroll
        for (int i = 0; i < 4; ++i) {
            int q = tid + i * 256;
            int r = q >> 3, c = (q & 7) * 4;
            cp16(so + (unsigned int)(r * G2ASTR + c) * 4u, arow[i] + k0 + c, 1);
        }
        #pragma unroll
        for (int i = 0; i < 4; ++i) {
            int q = tid + i * 256;
            int br = q >> 5, bcn = (q & 31) * 4;
            cp16(so + (unsigned int)(G2ASZ + br * G2BSTR + bcn) * 4u,
                 brow[i] + (size_t)k0 * ldb, bval[i]);
        }
        asm volatile("cp.async.commit_group;\n" ::: "memory");
    };

    const int nk = K / G2BK;
    #pragma unroll
    for (int s = 0; s < NS - 1; ++s) load_stage(s, s);

    const int wid = tid >> 5;
    const int wr = wid & 3;
    const int wc = wid >> 2;

    wmma::fragment<wmma::accumulator, 16, 16, 8, float> acc[2][4];
    #pragma unroll
    for (int i = 0; i < 2; ++i)
        #pragma unroll
        for (int j = 0; j < 4; ++j) wmma::fill_fragment(acc[i][j], 0.f);

    for (int kt = 0; kt < nk; ++kt) {
        asm volatile("cp.async.wait_group 1;\n" ::: "memory");
        __syncthreads();

        if (kt + NS - 1 < nk) load_stage(kt + NS - 1, (kt + NS - 1) % NS);
        else asm volatile("cp.async.commit_group;\n" ::: "memory");

        const float* Ab = dyn + (kt % NS) * G2STG;
        const float* Bb = Ab + G2ASZ;
        #pragma unroll
        for (int ks = 0; ks < 4; ++ks) {
            wmma::fragment<wmma::matrix_a, 16, 16, 8, wmma::precision::tf32, wmma::row_major> af[2];
            wmma::fragment<wmma::matrix_b, 16, 16, 8, wmma::precision::tf32, wmma::row_major> bf[4];
            #pragma unroll
            for (int i = 0; i < 2; ++i)
                wmma::load_matrix_sync(af[i], Ab + (wr * 32 + i * 16) * G2ASTR + ks * 8, G2ASTR);
            #pragma unroll
            for (int j = 0; j < 4; ++j)
                wmma::load_matrix_sync(bf[j], Bb + (ks * 8) * G2BSTR + wc * 64 + j * 16, G2BSTR);
            #pragma unroll
            for (int i = 0; i < 2; ++i)
                #pragma unroll
                for (int j = 0; j < 4; ++j)
                    wmma::mma_sync(acc[i][j], af[i], bf[j], acc[i][j]);
        }
    }
    asm volatile("cp.async.wait_group 0;\n" ::: "memory");
    __syncthreads();

    float* Cs = dyn;
    for (int chunk = 0; chunk < 4; ++chunk) {
        if (wr == chunk) {
            #pragma unroll
            for (int i = 0; i < 2; ++i)
                #pragma unroll
                for (int j = 0; j < 4; ++j)
                    wmma::store_matrix_sync(Cs + (i * 16) * G2BSTR + wc * 64 + j * 16,
                                            acc[i][j], G2BSTR, wmma::mem_row_major);
        }
        __syncthreads();
        #pragma unroll
        for (int it = 0; it < 16; ++it) {
            int idx = tid + it * 256;
            int r = idx >> 7, cn = idx & 127;
            int m = m0 + chunk * 32 + r;
            int n = n0 + cn;
            if (m < M && n < N) {
                float v = Cs[r * G2BSTR + cn] + bias[n];
                if (CMODE == 0) {
                    C[(size_t)m * ldc + n] = v;
                } else if (CMODE == 1) {
                    int bb = m & 63, tt = m >> 6;
                    C[((size_t)bb * TT + tt) * ldc + n] = v;
                } else {
                    if (n < 1024) g_scratch[OFF_SX + 512u + (unsigned)m * 1536u + (unsigned)n] = tf32r(v);
                    else          g_scratch[OFF_C + (unsigned)m * 1024u + (unsigned)(n - 1024)] = v;
                }
            }
        }
        __syncthreads();
    }
}

// ================= persistent recurrence kernel =================
#define NBLK 128
#define RKB 64
#define RASTR 68
#define RBSTR 36
#define RASZ (64 * RASTR)      // 4352
#define RBSZ (64 * RBSTR)      // 2304
#define RSTG (RASZ + RBSZ)     // 6656
#define RSMEM_FLOATS (3 * RSTG)          // 19968
#define RSMEM_BYTES  (RSMEM_FLOATS * 4)  // 79872

__device__ __forceinline__ void grid_sync(unsigned& gen)
{
    __syncthreads();
    if (threadIdx.x == 0) {
        __threadfence();
        unsigned arrived = atomicAdd(&g_bar_count, 1u);
        if (arrived == (unsigned)(NBLK - 1)) {
            g_bar_count = 0;
            __threadfence();
            atomicAdd(&g_bar_gen, 1u);
        } else {
            while (*(volatile unsigned*)&g_bar_gen == gen) __nanosleep(32);
            __threadfence();
        }
    }
    gen++;
    __syncthreads();
}

// 64x32 output tile, GBK=64, cp.async 3-stage, warp K-split (2 groups).
// Warp wid: kg=wid>>2 (k-group), nh=(wid>>1)&1 (n half 16), mh=wid&1 (m half 32).
__device__ __forceinline__ void tile_gemm_ws(
    const float* __restrict__ A, int lda,
    const float* __restrict__ B, int ldb, int K,
    float* sbuf,
    wmma::fragment<wmma::accumulator, 16, 16, 8, float>& acc0,
    wmma::fragment<wmma::accumulator, 16, 16, 8, float>& acc1)
{
    const int tid = threadIdx.x;
    const int wid = tid >> 5;
    const int kg = wid >> 2;
    const int nh = (wid >> 1) & 1;
    const int mh = wid & 1;
    const unsigned int sb = (unsigned int)__cvta_generic_to_shared(sbuf);
    const int nk = K >> 6;

    auto load_stage = [&](int kt, int s) {
        const unsigned int so = sb + (unsigned int)(s * RSTG) * 4u;
        const int k0 = kt * RKB;
        #pragma unroll
        for (int i = 0; i < 4; ++i) {               // A: 64 rows x 64 k
            int q = tid + i * 256;
            int r = q >> 4, c = (q & 15) * 4;
            cp16(so + (unsigned int)(r * RASTR + c) * 4u, A + (size_t)r * lda + k0 + c, 1);
        }
        #pragma unroll
        for (int i = 0; i < 2; ++i) {               // B: 64 k-rows x 32 cols
            int q = tid + i * 256;
            int r = q >> 3, c = (q & 7) * 4;
            cp16(so + (unsigned int)(RASZ + r * RBSTR + c) * 4u,
                 B + (size_t)(k0 + r) * ldb + c, 1);
        }
        asm volatile("cp.async.commit_group;\n" ::: "memory");
    };

    load_stage(0, 0);
    load_stage(1, 1);

    for (int kt = 0; kt < nk; ++kt) {
        asm volatile("cp.async.wait_group 1;\n" ::: "memory");
        __syncthreads();
        if (kt + 2 < nk) load_stage(kt + 2, (kt + 2) % 3);
        else asm volatile("cp.async.commit_group;\n" ::: "memory");

        const float* Ab = sbuf + (kt % 3) * RSTG;
        const float* Bb = Ab + RASZ;
        #pragma unroll
        for (int kk = 0; kk < 4; ++kk) {
            int k = kg * 32 + kk * 8;
            wmma::fragment<wmma::matrix_a, 16, 16, 8, wmma::precision::tf32, wmma::row_major> af0, af1;
            wmma::fragment<wmma::matrix_b, 16, 16, 8, wmma::precision::tf32, wmma::row_major> bf;
            wmma::load_matrix_sync(af0, Ab + (mh * 32) * RASTR + k, RASTR);
            wmma::load_matrix_sync(af1, Ab + (mh * 32 + 16) * RASTR + k, RASTR);
            wmma::load_matrix_sync(bf, Bb + k * RBSTR + nh * 16, RBSTR);
            wmma::mma_sync(acc0, af0, bf, acc0);
            wmma::mma_sync(acc1, af1, bf, acc1);
        }
    }
    asm volatile("cp.async.wait_group 0;\n" ::: "memory");
    __syncthreads();
}

__device__ __forceinline__ void tile_store_ws(
    float* sbuf,
    wmma::fragment<wmma::accumulator, 16, 16, 8, float>& acc0,
    wmma::fragment<wmma::accumulator, 16, 16, 8, float>& acc1)
{
    const int wid = threadIdx.x >> 5;
    const int kg = wid >> 2;
    const int nh = (wid >> 1) & 1;
    const int mh = wid & 1;
    float* Cs = sbuf + kg * 2304;
    wmma::store_matrix_sync(Cs + (mh * 32) * 36 + nh * 16, acc0, 36, wmma::mem_row_major);
    wmma::store_matrix_sync(Cs + (mh * 32 + 16) * 36 + nh * 16, acc1, 36, wmma::mem_row_major);
    __syncthreads();
}

__device__ __forceinline__ float sigm(float x) { return 1.f / (1.f + expf(-x)); }

__global__ __launch_bounds__(256, 1)
void recur_kernel(const float* __restrict__ enc,
                  const float* __restrict__ wfull,
                  const float* __restrict__ bfull,
                  float* __restrict__ alpha_out)
{
    extern __shared__ float sbuf[];

    const int bi = blockIdx.x;
    const int tid = threadIdx.x;
    const int wid = tid >> 5, lane = tid & 31;

    float* S = g_scratch;
    const float* att_enc = S + OFF_ATT_ENC;
    const float* Wcat    = S + OFF_WCAT;
    const float* bcat    = S + OFF_BCAT;
    const float* Wrec    = S + OFF_WREC;
    const float* ebias   = S + OFF_EBIAS;
    float* sx            = S + OFF_SX;
    float* cbuf          = S + OFF_C;
    float* attdec        = S + OFF_ATTDEC;
    float* hall          = S + OFF_HALL;

    unsigned gen = *(volatile unsigned*)&g_bar_gen;
    const float bf0 = bfull[0];

    for (int t = 0; t < TT; ++t) {
        const int cur = t & 1, nxt = cur ^ 1;
        float* sxc = sx + cur * (64 * 1536);
        float* sxn = sx + nxt * (64 * 1536);

        // ---- P1: attdec = h @ Wcat + bcat (blocks 0..31) ----
        if (bi < 32) {
            wmma::fragment<wmma::accumulator, 16, 16, 8, float> a0, a1;
            wmma::fill_fragment(a0, 0.f);
            wmma::fill_fragment(a1, 0.f);
            tile_gemm_ws(sxc + 512, 1536, Wcat + bi * 32, 1024, HH, sbuf, a0, a1);
            tile_store_ws(sbuf, a0, a1);
            const int n0 = bi * 32;
            #pragma unroll
            for (int i = 0; i < 8; ++i) {
                int idx = tid + i * 256;
                int r = idx >> 5, c = idx & 31;
                attdec[r * 1024 + n0 + c] = sbuf[r * 36 + c] + sbuf[2304 + r * 36 + c] + bcat[n0 + c];
            }
        }
        grid_sync(gen);

        // ---- P2: attention (blocks 0..63) ----
        if (bi < 64) {
            const int b = bi;
            float* sa   = sbuf;          // 512
            float* sw   = sbuf + 512;    // 512
            float* se   = sbuf + 1024;   // 196 (alpha)
            float* sred = sbuf + 1248;   // 32
            float* sctx = sbuf + 1280;   // 2*512 partial context

            for (int i = tid; i < AA; i += 256) {
                sa[i] = attdec[b * 1024 + i];
                sw[i] = wfull[i];
            }
            __syncthreads();

            for (int p = wid; p < PP; p += 8) {
                const float* row = att_enc + (size_t)(b * PP + p) * AA;
                float acc = 0.f;
                #pragma unroll 4
                for (int a = lane; a < AA; a += 32) {
                    float x = row[a] + sa[a];
                    x = x > 0.f ? x : 0.f;
                    acc += x * sw[a];
                }
                #pragma unroll
                for (int o = 16; o; o >>= 1) acc += __shfl_xor_sync(0xffffffffu, acc, o);
                if (lane == 0) se[p] = acc + bf0;
            }
            __syncthreads();

            float v = (tid < PP) ? se[tid] : -1e30f;
            float m = v;
            #pragma unroll
            for (int o = 16; o; o >>= 1) m = fmaxf(m, __shfl_xor_sync(0xffffffffu, m, o));
            if (lane == 0) sred[wid] = m;
            __syncthreads();
            if (wid == 0) {
                float mm = (lane < 8) ? sred[lane] : -1e30f;
                #pragma unroll
                for (int o = 16; o; o >>= 1) mm = fmaxf(mm, __shfl_xor_sync(0xffffffffu, mm, o));
                if (lane == 0) sred[0] = mm;
            }
            __syncthreads();
            float mx = sred[0];
            __syncthreads();

            float ex = (tid < PP) ? expf(v - mx) : 0.f;
            float s = ex;
            #pragma unroll
            for (int o = 16; o; o >>= 1) s += __shfl_xor_sync(0xffffffffu, s, o);
            if (lane == 0) sred[wid] = s;
            __syncthreads();
            if (wid == 0) {
                float ss = (lane < 8) ? sred[lane] : 0.f;
                #pragma unroll
                for (int o = 16; o; o >>= 1) ss += __shfl_xor_sync(0xffffffffu, ss, o);
                if (lane == 0) sred[0] = ss;
            }
            __syncthreads();
            float inv = 1.f / sred[0];

            if (tid < PP) {
                float al = ex * inv;
                se[tid] = al;
                alpha_out[((size_t)b * TT + t) * PP + tid] = al;
            }
            __syncthreads();

            // context: 2 p-groups x 128 threads, float4 over e
            {
                int grp = tid >> 7;
                int t2 = tid & 127;
                const float* base = enc + ((size_t)(b * PP) + grp * 98) * ENC + t2 * 4;
                const float* al = se + grp * 98;
                float4 acc4 = make_float4(0.f, 0.f, 0.f, 0.f);
                #pragma unroll 7
                for (int p = 0; p < 98; ++p) {
                    float a = al[p];
                    float4 vv = *(const float4*)(base + (size_t)p * ENC);
                    acc4.x += a * vv.x; acc4.y += a * vv.y;
                    acc4.z += a * vv.z; acc4.w += a * vv.w;
                }
                *(float4*)&sctx[grp * 512 + t2 * 4] = acc4;
            }
            __syncthreads();
            if (tid < 128) {
                float4 c0 = *(float4*)&sctx[tid * 4];
                float4 c1 = *(float4*)&sctx[512 + tid * 4];
                const float* fb = attdec + b * 1024 + 512 + tid * 4;
                float4 o;
                o.x = tf32r(sigm(fb[0]) * (c0.x + c1.x));
                o.y = tf32r(sigm(fb[1]) * (c0.y + c1.y));
                o.z = tf32r(sigm(fb[2]) * (c0.z + c1.z));
                o.w = tf32r(sigm(fb[3]) * (c0.w + c1.w));
                *(float4*)&sxc[b * 1536 + tid * 4] = o;
            }
        }
        grid_sync(gen);

        // ---- P3: gates + fused LSTM (all 128 blocks) ----
        {
            wmma::fragment<wmma::accumulator, 16, 16, 8, float> a0, a1;
            wmma::fill_fragment(a0, 0.f);
            wmma::fill_fragment(a1, 0.f);
            const int n0 = bi * 32;
            tile_gemm_ws(sxc, 1536, Wrec + n0, 4096, ENC + HH, sbuf, a0, a1);
            tile_store_ws(sbuf, a0, a1);

            #pragma unroll
            for (int i = 0; i < 2; ++i) {
                int p = tid + i * 256;
                int b = p >> 3, jj = p & 7;
                int j = bi * 8 + jj;
                float4 g0 = *(float4*)&sbuf[b * 36 + jj * 4];
                float4 g1 = *(float4*)&sbuf[2304 + b * 36 + jj * 4];
                float4 e = *(const float4*)&ebias[((size_t)t * BB + b) * 4096 + n0 + jj * 4];
                float gi = g0.x + g1.x + e.x, gf = g0.y + g1.y + e.y;
                float gg = g0.z + g1.z + e.z, go = g0.w + g1.w + e.w;
                float co = cbuf[b * 1024 + j];
                float cn = sigm(gf) * co + sigm(gi) * tanhf(gg);
                float h  = sigm(go) * tanhf(cn);
                float hr = tf32r(h);
                cbuf[b * 1024 + j] = cn;
                sxn[b * 1536 + 512 + j] = hr;
                hall[((size_t)t * BB + b) * 1024 + j] = hr;
            }
        }
        grid_sync(gen);
    }
}

// ---------------- launch ----------------
extern "C" void kernel_launch(void* const* d_in, const int* in_sizes, int n_in,
                              void* d_out, int out_size)
{
    const float* enc       = (const float*)d_in[0];
    const int*   caps      = (const int*)  d_in[1];
    const float* W_enc_att = (const float*)d_in[3];
    const float* b_enc_att = (const float*)d_in[4];
    const float* W_dec_att = (const float*)d_in[5];
    const float* b_dec_att = (const float*)d_in[6];
    const float* W_full    = (const float*)d_in[7];
    const float* b_full    = (const float*)d_in[8];
    const float* emb       = (const float*)d_in[9];
    const float* W_ih      = (const float*)d_in[10];
    const float* b_ih      = (const float*)d_in[11];
    const float* W_hh      = (const float*)d_in[12];
    const float* b_hh      = (const float*)d_in[13];
    const float* W_init_h  = (const float*)d_in[14];
    const float* b_init_h  = (const float*)d_in[15];
    const float* W_init_c  = (const float*)d_in[16];
    const float* b_init_c  = (const float*)d_in[17];
    const float* W_fbeta   = (const float*)d_in[18];
    const float* b_fbeta   = (const float*)d_in[19];
    const float* W_fc      = (const float*)d_in[20];
    const float* b_fc      = (const float*)d_in[21];

    float* out = (float*)d_out;
    float* alpha_out = out + (size_t)BB * TT * VV;

    void* sp = nullptr;
    cudaGetSymbolAddress(&sp, g_scratch);
    float* S = (float*)sp;

    cudaFuncSetAttribute(gemm2<0>, cudaFuncAttributeMaxDynamicSharedMemorySize, G2_SMEM_BYTES);
    cudaFuncSetAttribute(gemm2<1>, cudaFuncAttributeMaxDynamicSharedMemorySize, G2_SMEM_BYTES);
    cudaFuncSetAttribute(gemm2<2>, cudaFuncAttributeMaxDynamicSharedMemorySize, G2_SMEM_BYTES);
    cudaFuncSetAttribute(recur_kernel, cudaFuncAttributeMaxDynamicSharedMemorySize, RSMEM_BYTES);

    // 1. prep (weights pack/round + enc round + emb gather + mean)
    prep_kernel<<<2048, 256>>>(W_dec_att, W_fbeta, b_dec_att, b_fbeta, W_ih, W_hh, b_ih, b_hh,
                               enc, emb, W_fc, W_enc_att, W_init_h, W_init_c,
                               b_init_h, b_init_c, caps);

    // 2. [h0 | c0] = mean @ W0 + b0 (split epilogue)
    gemm2<2><<<dim3(16, 1), 256, G2_SMEM_BYTES>>>(
        S + OFF_MEAN, ENC, S + OFF_W0, 2048, S, 0, S + OFF_B0, BB, 2048, ENC);

    // 3. att_enc = enc_r @ W_enc_att_r + b_enc_att
    gemm2<0><<<dim3(4, 98), 256, G2_SMEM_BYTES>>>(
        S + OFF_ENC_R, ENC, S + OFF_WEA_R, AA,
        S + OFF_ATT_ENC, AA, b_enc_att, BB * PP, AA, ENC);

    // 4. ebias = embg @ Wih_perm + brec (permuted cols)
    gemm2<0><<<dim3(32, 12), 256, G2_SMEM_BYTES>>>(
        S + OFF_EMBG, EE, S + OFF_WIH, 4096,
        S + OFF_EBIAS, 4096, S + OFF_BREC, TT * BB, 4096, EE);

    // 5. persistent 24-step recurrence
    recur_kernel<<<NBLK, 256, RSMEM_BYTES>>>(enc, W_full, b_full, alpha_out);

    // 6. predictions = hall @ W_fc_r + b_fc (remapped to (B,T,V))
    gemm2<1><<<dim3(157, 12), 256, G2_SMEM_BYTES>>>(
        S + OFF_HALL, HH, S + OFF_WFC_R, VV,
        out, VV, b_fc, TT * BB, VV, HH);
}

// round 10
// speedup vs baseline: 3.1359x; 2.0619x over previous
#include <cuda_runtime.h>
#include <cuda_fp16.h>
#include <mma.h>
#include <math.h>
#include <cstdint>

using namespace nvcuda;

// ---------------- problem constants ----------------
#define BB    64
#define PP    196
#define ENC   512
#define EE    1024
#define HH    1024
#define AA    512
#define VV    20000
#define LL    25
#define TT    24

// ---------------- scratch layout (float units; half regions cast) ----------------
#define OFF_ATT_ENC  0u            // fp32 12544*512
#define OFF_EBIAS    6422528u      // fp32 1536*4096
#define OFF_WREC     12713984u     // half 1536*4096 (col-permuted)
#define OFF_WIH      15859712u     // half 1024*4096 (col-permuted)
#define OFF_WCAT     17956864u     // half 1024*1024
#define OFF_BCAT     18481152u     // fp32 1024
#define OFF_BREC     18482176u     // fp32 4096
#define OFF_MEAN     18486272u     // half 64*512
#define OFF_SX       18502656u     // half 2*64*1536 ([gc|h])
#define OFF_C        18600960u     // fp32 64*1024
#define OFF_ATTDEC   18666496u     // fp32 64*1024
#define OFF_HALL     18732032u     // half 1536*1024
#define OFF_ENC_H    19518464u     // half 12544*512
#define OFF_EMBG     22729728u     // half 1536*1024
#define OFF_WFC_H    23516160u     // half 1024*20000
#define OFF_WEA_H    33756160u     // half 512*512
#define OFF_W0       33887232u     // half 512*2048 ([W_init_h | W_init_c])
#define OFF_B0       34411520u     // fp32 2048
#define SCRATCH_TOTAL 34413568u

__device__ __align__(256) float g_scratch[SCRATCH_TOTAL];

__device__ unsigned g_bar_count = 0;
__device__ unsigned g_bar_gen   = 0;

__device__ __forceinline__ void cp16(unsigned int dst, const void* src, int pred)
{
    asm volatile(
        "{\n\t.reg .pred p;\n\t"
        "setp.ne.b32 p, %2, 0;\n\t"
        "@p cp.async.cg.shared.global [%0], [%1], 16;\n\t}\n"
        :: "r"(dst), "l"(src), "r"(pred));
}

// ---------------- prep ----------------
__global__ void prep_kernel(const float* __restrict__ Wdec, const float* __restrict__ Wfb,
                            const float* __restrict__ bdec, const float* __restrict__ bfb,
                            const float* __restrict__ Wih,  const float* __restrict__ Whh,
                            const float* __restrict__ bih,  const float* __restrict__ bhh,
                            const float* __restrict__ enc,  const float* __restrict__ emb,
                            const float* __restrict__ Wfc,  const float* __restrict__ Wea,
                            const float* __restrict__ Wih0, const float* __restrict__ Wic0,
                            const float* __restrict__ bih0, const float* __restrict__ bic0,
                            const int*   __restrict__ caps)
{
    __half* Wcat = (__half*)(g_scratch + OFF_WCAT);
    float*  bcat = g_scratch + OFF_BCAT;
    __half* Wrec = (__half*)(g_scratch + OFF_WREC);
    __half* Wihp = (__half*)(g_scratch + OFF_WIH);
    float*  brec = g_scratch + OFF_BREC;
    __half* ench = (__half*)(g_scratch + OFF_ENC_H);
    __half* embg = (__half*)(g_scratch + OFF_EMBG);
    __half* wfch = (__half*)(g_scratch + OFF_WFC_H);
    __half* weah = (__half*)(g_scratch + OFF_WEA_H);
    __half* w0   = (__half*)(g_scratch + OFF_W0);
    float*  b0   = g_scratch + OFF_B0;
    __half* mean = (__half*)(g_scratch + OFF_MEAN);

    int i = blockIdx.x * blockDim.x + threadIdx.x;
    int stride = gridDim.x * blockDim.x;

    for (int idx = i; idx < 1024 * 1024; idx += stride) {
        int k = idx >> 10, c = idx & 1023;
        Wcat[idx] = __float2half_rn((c < 512) ? Wdec[k * 512 + c] : Wfb[k * 512 + (c - 512)]);
    }
    for (int idx = i; idx < 1024; idx += stride)
        bcat[idx] = (idx < 512) ? bdec[idx] : bfb[idx - 512];

    for (int idx = i; idx < 1536 * 4096; idx += stride) {
        int r = idx >> 12, cp = idx & 4095;
        int j = cp >> 2, q = cp & 3;
        int oc = q * 1024 + j;
        Wrec[idx] = __float2half_rn((r < 512) ? Wih[(size_t)(1024 + r) * 4096 + oc]
                                              : Whh[(size_t)(r - 512) * 4096 + oc]);
    }
    for (int idx = i; idx < 1024 * 4096; idx += stride) {
        int r = idx >> 12, cp = idx & 4095;
        int j = cp >> 2, q = cp & 3;
        Wihp[idx] = __float2half_rn(Wih[(size_t)r * 4096 + q * 1024 + j]);
    }
    for (int idx = i; idx < 4096; idx += stride) {
        int j = idx >> 2, q = idx & 3;
        brec[idx] = bih[q * 1024 + j] + bhh[q * 1024 + j];
    }
    for (int idx = i; idx < (BB * PP * ENC) / 2; idx += stride) {
        float2 v = ((const float2*)enc)[idx];
        ((__half2*)ench)[idx] = __floats2half2_rn(v.x, v.y);
    }
    for (int idx = i; idx < TT * BB * EE; idx += stride) {
        int m = idx >> 10, c = idx & 1023;
        int tt = m >> 6, bb = m & 63;
        embg[idx] = __float2half_rn(emb[(size_t)caps[bb * LL + tt] * EE + c]);
    }
    for (int idx = i; idx < (HH * VV) / 2; idx += stride) {
        float2 v = ((const float2*)Wfc)[idx];
        ((__half2*)wfch)[idx] = __floats2half2_rn(v.x, v.y);
    }
    for (int idx = i; idx < ENC * AA; idx += stride) weah[idx] = __float2half_rn(Wea[idx]);
    for (int idx = i; idx < 512 * 2048; idx += stride) {
        int r = idx >> 11, c = idx & 2047;
        w0[idx] = __float2half_rn((c < 1024) ? Wih0[r * 1024 + c] : Wic0[r * 1024 + (c - 1024)]);
    }
    for (int idx = i; idx < 2048; idx += stride)
        b0[idx] = (idx < 1024) ? bih0[idx] : bic0[idx - 1024];
    for (int idx = i; idx < BB * ENC; idx += stride) {
        int b = idx >> 9, e = idx & 511;
        float s = 0.f;
        const float* base = enc + (size_t)(b * PP) * ENC + e;
        #pragma unroll 4
        for (int p = 0; p < PP; ++p) s += base[(size_t)p * ENC];
        mean[idx] = __float2half_rn(s * (1.f / (float)PP));
    }
}

// ====== gemm2 fp16: 128x128 tile, 8 warps (32x64), cp.async 4-stage ======
// CMODE 0: plain fp32 C;  1: preds remap;  2: init split (h half / c fp32)
#define NS   4
#define G2ASTR 40
#define G2BSTR 136
#define G2ASZ (128 * G2ASTR)   // 5120 halves
#define G2BSZ (32 * G2BSTR)    // 4352 halves
#define G2STG (G2ASZ + G2BSZ)  // 9472 halves
#define G2_SMEM_BYTES (NS * G2STG * 2)   // 75776

template<int CMODE>
__global__ __launch_bounds__(256, 2)
void gemm2(const __half* __restrict__ A, int lda,
           const __half* __restrict__ B, int ldb,
           float* __restrict__ C, int ldc,
           const float* __restrict__ bias,
           int M, int N, int K)
{
    extern __shared__ __half dynh[];
    float* dynf = (float*)dynh;

    const int tid = threadIdx.x;
    const int n0 = blockIdx.x * 128;
    const int m0 = blockIdx.y * 128;

    const __half* arow[2];
    const __half* brow[2];
    int bval[2];
    #pragma unroll
    for (int i = 0; i < 2; ++i) {
        int q = tid + i * 256;
        int r = q >> 2;                   // 0..127
        int gr = m0 + r; if (gr >= M) gr = M - 1;
        arow[i] = A + (size_t)gr * lda + (q & 3) * 8;
        int br = q >> 4;                  // 0..31
        int bcn = (q & 15) * 8;           // 0..120
        brow[i] = B + (size_t)br * ldb + n0 + bcn;
        bval[i] = (n0 + bcn) < N;
    }
    const unsigned int sbase = (unsigned int)__cvta_generic_to_shared(dynh);

    auto load_stage = [&](int kt, int s) {
        const unsigned int so = sbase + (unsigned int)(s * G2STG) * 2u;
        const int k0 = kt * 32;
        #pragma unroll
        for (int i = 0; i < 2; ++i) {
            int q = tid + i * 256;
            int r = q >> 2, c = (q & 3) * 8;
            cp16(so + (unsigned int)(r * G2ASTR + c) * 2u, arow[i] + k0, 1);
        }
        #pragma unroll
        for (int i = 0; i < 2; ++i) {
            int q = tid + i * 256;
            int br = q >> 4, bcn = (q & 15) * 8;
            cp16(so + (unsigned int)(G2ASZ + br * G2BSTR + bcn) * 2u,
                 brow[i] + (size_t)k0 * ldb, bval[i]);
        }
        asm volatile("cp.async.commit_group;\n" ::: "memory");
    };

    const int nk = K >> 5;
    #pragma unroll
    for (int s = 0; s < NS - 1; ++s) load_stage(s, s);

    const int wid = tid >> 5;
    const int wr = wid & 3;    // m 32-chunks
    const int wc = wid >> 2;   // n 64-chunks

    wmma::fragment<wmma::accumulator, 16, 16, 16, float> acc[2][4];
    #pragma unroll
    for (int i = 0; i < 2; ++i)
        #pragma unroll
        for (int j = 0; j < 4; ++j) wmma::fill_fragment(acc[i][j], 0.f);

    for (int kt = 0; kt < nk; ++kt) {
        asm volatile("cp.async.wait_group 2;\n" ::: "memory");
        __syncthreads();

        if (kt + NS - 1 < nk) load_stage(kt + NS - 1, (kt + NS - 1) % NS);
        else asm volatile("cp.async.commit_group;\n" ::: "memory");

        const __half* Ab = dynh + (kt % NS) * G2STG;
        const __half* Bb = Ab + G2ASZ;
        #pragma unroll
        for (int ks = 0; ks < 2; ++ks) {
            wmma::fragment<wmma::matrix_a, 16, 16, 16, __half, wmma::row_major> af[2];
            #pragma unroll
            for (int i = 0; i < 2; ++i)
                wmma::load_matrix_sync(af[i], Ab + (wr * 32 + i * 16) * G2ASTR + ks * 16, G2ASTR);
            #pragma unroll
            for (int j = 0; j < 4; ++j) {
                wmma::fragment<wmma::matrix_b, 16, 16, 16, __half, wmma::row_major> bf;
                wmma::load_matrix_sync(bf, Bb + (ks * 16) * G2BSTR + wc * 64 + j * 16, G2BSTR);
                wmma::mma_sync(acc[0][j], af[0], bf, acc[0][j]);
                wmma::mma_sync(acc[1][j], af[1], bf, acc[1][j]);
            }
        }
    }
    asm volatile("cp.async.wait_group 0;\n" ::: "memory");
    __syncthreads();

    float* Cs = dynf;   // 32 x 132
    for (int chunk = 0; chunk < 4; ++chunk) {
        if (wr == chunk) {
            #pragma unroll
            for (int i = 0; i < 2; ++i)
                #pragma unroll
                for (int j = 0; j < 4; ++j)
                    wmma::store_matrix_sync(Cs + (i * 16) * 132 + wc * 64 + j * 16,
                                            acc[i][j], 132, wmma::mem_row_major);
        }
        __syncthreads();
        #pragma unroll
        for (int it = 0; it < 16; ++it) {
            int idx = tid + it * 256;
            int r = idx >> 7, cn = idx & 127;
            int m = m0 + chunk * 32 + r;
            int n = n0 + cn;
            if (m < M && n < N) {
                float v = Cs[r * 132 + cn] + bias[n];
                if (CMODE == 0) {
                    C[(size_t)m * ldc + n] = v;
                } else if (CMODE == 1) {
                    int bb = m & 63, tt = m >> 6;
                    C[((size_t)bb * TT + tt) * ldc + n] = v;
                } else {
                    if (n < 1024)
                        ((__half*)(g_scratch + OFF_SX))[(unsigned)m * 1536u + 512u + (unsigned)n] = __float2half_rn(v);
                    else
                        g_scratch[OFF_C + (unsigned)m * 1024u + (unsigned)(n - 1024)] = v;
                }
            }
        }
        __syncthreads();
    }
}

// ================= persistent recurrence kernel =================
#define NBLK 128
#define RASTR 72
#define RBSTR 40
#define RASZ (64 * RASTR)      // 4608 halves
#define RBSZ (64 * RBSTR)      // 2560 halves
#define RSTG (RASZ + RBSZ)     // 7168 halves
#define RSMEM_BYTES (3 * RSTG * 2)   // 43008

__device__ __forceinline__ void grid_sync(unsigned& gen)
{
    __syncthreads();
    if (threadIdx.x == 0) {
        __threadfence();
        unsigned arrived = atomicAdd(&g_bar_count, 1u);
        if (arrived == (unsigned)(NBLK - 1)) {
            g_bar_count = 0;
            __threadfence();
            atomicAdd(&g_bar_gen, 1u);
        } else {
            while (*(volatile unsigned*)&g_bar_gen == gen) __nanosleep(32);
            __threadfence();
        }
    }
    gen++;
    __syncthreads();
}

// 64x32 tile, K-block 64, cp.async 3-stage, warp K-split (2 groups).
__device__ __forceinline__ void tile_gemm_ws(
    const __half* __restrict__ A, int lda,
    const __half* __restrict__ B, int ldb, int K,
    __half* sbufh,
    wmma::fragment<wmma::accumulator, 16, 16, 16, float>& acc0,
    wmma::fragment<wmma::accumulator, 16, 16, 16, float>& acc1)
{
    const int tid = threadIdx.x;
    const int wid = tid >> 5;
    const int kg = wid >> 2;
    const int nh = (wid >> 1) & 1;
    const int mh = wid & 1;
    const unsigned int sb = (unsigned int)__cvta_generic_to_shared(sbufh);
    const int nk = K >> 6;

    auto load_stage = [&](int kt, int s) {
        const unsigned int so = sb + (unsigned int)(s * RSTG) * 2u;
        const int k0 = kt * 64;
        #pragma unroll
        for (int i = 0; i < 2; ++i) {               // A: 64 rows x 64 halves
            int q = tid + i * 256;
            int r = q >> 3, c = (q & 7) * 8;
            cp16(so + (unsigned int)(r * RASTR + c) * 2u, A + (size_t)r * lda + k0 + c, 1);
        }
        {                                           // B: 64 k-rows x 32 halves
            int r = tid >> 2, c = (tid & 3) * 8;
            cp16(so + (unsigned int)(RASZ + r * RBSTR + c) * 2u,
                 B + (size_t)(k0 + r) * ldb + c, 1);
        }
        asm volatile("cp.async.commit_group;\n" ::: "memory");
    };

    load_stage(0, 0);
    load_stage(1, 1);

    for (int kt = 0; kt < nk; ++kt) {
        asm volatile("cp.async.wait_group 1;\n" ::: "memory");
        __syncthreads();
        if (kt + 2 < nk) load_stage(kt + 2, (kt + 2) % 3);
        else asm volatile("cp.async.commit_group;\n" ::: "memory");

        const __half* Ab = sbufh + (kt % 3) * RSTG;
        const __half* Bb = Ab + RASZ;
        #pragma unroll
        for (int kk = 0; kk < 2; ++kk) {
            int k = kg * 32 + kk * 16;
            wmma::fragment<wmma::matrix_a, 16, 16, 16, __half, wmma::row_major> af0, af1;
            wmma::fragment<wmma::matrix_b, 16, 16, 16, __half, wmma::row_major> bf;
            wmma::load_matrix_sync(af0, Ab + (mh * 32) * RASTR + k, RASTR);
            wmma::load_matrix_sync(af1, Ab + (mh * 32 + 16) * RASTR + k, RASTR);
            wmma::load_matrix_sync(bf, Bb + k * RBSTR + nh * 16, RBSTR);
            wmma::mma_sync(acc0, af0, bf, acc0);
            wmma::mma_sync(acc1, af1, bf, acc1);
        }
    }
    asm volatile("cp.async.wait_group 0;\n" ::: "memory");
    __syncthreads();
}

__device__ __forceinline__ void tile_store_ws(
    float* sbuff,
    wmma::fragment<wmma::accumulator, 16, 16, 16, float>& acc0,
    wmma::fragment<wmma::accumulator, 16, 16, 16, float>& acc1)
{
    const int wid = threadIdx.x >> 5;
    const int kg = wid >> 2;
    const int nh = (wid >> 1) & 1;
    const int mh = wid & 1;
    float* Cs = sbuff + kg * 2304;
    wmma::store_matrix_sync(Cs + (mh * 32) * 36 + nh * 16, acc0, 36, wmma::mem_row_major);
    wmma::store_matrix_sync(Cs + (mh * 32 + 16) * 36 + nh * 16, acc1, 36, wmma::mem_row_major);
    __syncthreads();
}

__device__ __forceinline__ float sigm(float x) { return 1.f / (1.f + expf(-x)); }

__global__ __launch_bounds__(256, 1)
void recur_kernel(const float* __restrict__ enc,
                  const float* __restrict__ wfull,
                  const float* __restrict__ bfull,
                  float* __restrict__ alpha_out)
{
    extern __shared__ __half sbufh[];
    float* sbuff = (float*)sbufh;

    const int bi = blockIdx.x;
    const int tid = threadIdx.x;
    const int wid = tid >> 5, lane = tid & 31;

    float* S = g_scratch;
    const float*  att_enc = S + OFF_ATT_ENC;
    const __half* Wcat    = (const __half*)(S + OFF_WCAT);
    const float*  bcat    = S + OFF_BCAT;
    const __half* Wrec    = (const __half*)(S + OFF_WREC);
    const float*  ebias   = S + OFF_EBIAS;
    __half* sxh           = (__half*)(S + OFF_SX);
    float* cbuf           = S + OFF_C;
    float* attdec         = S + OFF_ATTDEC;
    __half* hall          = (__half*)(S + OFF_HALL);

    unsigned gen = *(volatile unsigned*)&g_bar_gen;
    const float bf0 = bfull[0];

    for (int t = 0; t < TT; ++t) {
        const int cur = t & 1, nxt = cur ^ 1;
        __half* sxc = sxh + cur * (64 * 1536);
        __half* sxn = sxh + nxt * (64 * 1536);

        // ---- P1: attdec = h @ Wcat + bcat (blocks 0..31) ----
        if (bi < 32) {
            wmma::fragment<wmma::accumulator, 16, 16, 16, float> a0, a1;
            wmma::fill_fragment(a0, 0.f);
            wmma::fill_fragment(a1, 0.f);
            tile_gemm_ws(sxc + 512, 1536, Wcat + bi * 32, 1024, HH, sbufh, a0, a1);
            tile_store_ws(sbuff, a0, a1);
            const int n0 = bi * 32;
            #pragma unroll
            for (int i = 0; i < 8; ++i) {
                int idx = tid + i * 256;
                int r = idx >> 5, c = idx & 31;
                attdec[r * 1024 + n0 + c] = sbuff[r * 36 + c] + sbuff[2304 + r * 36 + c] + bcat[n0 + c];
            }
        }
        grid_sync(gen);

        // ---- P2: attention (blocks 0..63) ----
        if (bi < 64) {
            const int b = bi;
            float* sa   = sbuff;         // 512
            float* sw   = sbuff + 512;   // 512
            float* se   = sbuff + 1024;  // 196
            float* sred = sbuff + 1248;  // 32
            float* sctx = sbuff + 1280;  // 2*512

            for (int i = tid; i < AA; i += 256) {
                sa[i] = attdec[b * 1024 + i];
                sw[i] = wfull[i];
            }
            __syncthreads();

            for (int p = wid; p < PP; p += 8) {
                const float* row = att_enc + (size_t)(b * PP + p) * AA;
                float acc = 0.f;
                #pragma unroll 4
                for (int a = lane; a < AA; a += 32) {
                    float x = row[a] + sa[a];
                    x = x > 0.f ? x : 0.f;
                    acc += x * sw[a];
                }
                #pragma unroll
                for (int o = 16; o; o >>= 1) acc += __shfl_xor_sync(0xffffffffu, acc, o);
                if (lane == 0) se[p] = acc + bf0;
            }
            __syncthreads();

            float v = (tid < PP) ? se[tid] : -1e30f;
            float m = v;
            #pragma unroll
            for (int o = 16; o; o >>= 1) m = fmaxf(m, __shfl_xor_sync(0xffffffffu, m, o));
            if (lane == 0) sred[wid] = m;
            __syncthreads();
            if (wid == 0) {
                float mm = (lane < 8) ? sred[lane] : -1e30f;
                #pragma unroll
                for (int o = 16; o; o >>= 1) mm = fmaxf(mm, __shfl_xor_sync(0xffffffffu, mm, o));
                if (lane == 0) sred[0] = mm;
            }
            __syncthreads();
            float mx = sred[0];
            __syncthreads();

            float ex = (tid < PP) ? expf(v - mx) : 0.f;
            float s = ex;
            #pragma unroll
            for (int o = 16; o; o >>= 1) s += __shfl_xor_sync(0xffffffffu, s, o);
            if (lane == 0) sred[wid] = s;
            __syncthreads();
            if (wid == 0) {
                float ss = (lane < 8) ? sred[lane] : 0.f;
                #pragma unroll
                for (int o = 16; o; o >>= 1) ss += __shfl_xor_sync(0xffffffffu, ss, o);
                if (lane == 0) sred[0] = ss;
            }
            __syncthreads();
            float inv = 1.f / sred[0];

            if (tid < PP) {
                float al = ex * inv;
                se[tid] = al;
                alpha_out[((size_t)b * TT + t) * PP + tid] = al;
            }
            __syncthreads();

            // context: 2 p-groups x 128 threads, float4 over e
            {
                int grp = tid >> 7;
                int t2 = tid & 127;
                const float* base = enc + ((size_t)(b * PP) + grp * 98) * ENC + t2 * 4;
                const float* al = se + grp * 98;
                float4 acc4 = make_float4(0.f, 0.f, 0.f, 0.f);
                #pragma unroll 7
                for (int p = 0; p < 98; ++p) {
                    float a = al[p];
                    float4 vv = *(const float4*)(base + (size_t)p * ENC);
                    acc4.x += a * vv.x; acc4.y += a * vv.y;
                    acc4.z += a * vv.z; acc4.w += a * vv.w;
                }
                *(float4*)&sctx[grp * 512 + t2 * 4] = acc4;
            }
            __syncthreads();
            if (tid < 128) {
                float4 c0 = *(float4*)&sctx[tid * 4];
                float4 c1 = *(float4*)&sctx[512 + tid * 4];
                const float* fb = attdec + b * 1024 + 512 + tid * 4;
                __half2 h01 = __floats2half2_rn(sigm(fb[0]) * (c0.x + c1.x),
                                                sigm(fb[1]) * (c0.y + c1.y));
                __half2 h23 = __floats2half2_rn(sigm(fb[2]) * (c0.z + c1.z),
                                                sigm(fb[3]) * (c0.w + c1.w));
                *(__half2*)&sxc[b * 1536 + tid * 4]     = h01;
                *(__half2*)&sxc[b * 1536 + tid * 4 + 2] = h23;
            }
        }
        grid_sync(gen);

        // ---- P3: gates + fused LSTM (all 128 blocks) ----
        {
            wmma::fragment<wmma::accumulator, 16, 16, 16, float> a0, a1;
            wmma::fill_fragment(a0, 0.f);
            wmma::fill_fragment(a1, 0.f);
            const int n0 = bi * 32;
            tile_gemm_ws(sxc, 1536, Wrec + n0, 4096, ENC + HH, sbufh, a0, a1);
            tile_store_ws(sbuff, a0, a1);

            #pragma unroll
            for (int i = 0; i < 2; ++i) {
                int p = tid + i * 256;
                int b = p >> 3, jj = p & 7;
                int j = bi * 8 + jj;
                float4 g0 = *(float4*)&sbuff[b * 36 + jj * 4];
                float4 g1 = *(float4*)&sbuff[2304 + b * 36 + jj * 4];
                float4 e = *(const float4*)&ebias[((size_t)t * BB + b) * 4096 + n0 + jj * 4];
                float gi = g0.x + g1.x + e.x, gf = g0.y + g1.y + e.y;
                float gg = g0.z + g1.z + e.z, go = g0.w + g1.w + e.w;
                float co = cbuf[b * 1024 + j];
                float cn = sigm(gf) * co + sigm(gi) * tanhf(gg);
                float h  = sigm(go) * tanhf(cn);
                __half hr = __float2half_rn(h);
                cbuf[b * 1024 + j] = cn;
                sxn[b * 1536 + 512 + j] = hr;
                hall[((size_t)t * BB + b) * 1024 + j] = hr;
            }
        }
        grid_sync(gen);
    }
}

// ---------------- launch ----------------
extern "C" void kernel_launch(void* const* d_in, const int* in_sizes, int n_in,
                              void* d_out, int out_size)
{
    const float* enc       = (const float*)d_in[0];
    const int*   caps      = (const int*)  d_in[1];
    const float* W_enc_att = (const float*)d_in[3];
    const float* b_enc_att = (const float*)d_in[4];
    const float* W_dec_att = (const float*)d_in[5];
    const float* b_dec_att = (const float*)d_in[6];
    const float* W_full    = (const float*)d_in[7];
    const float* b_full    = (const float*)d_in[8];
    const float* emb       = (const float*)d_in[9];
    const float* W_ih      = (const float*)d_in[10];
    const float* b_ih      = (const float*)d_in[11];
    const float* W_hh      = (const float*)d_in[12];
    const float* b_hh      = (const float*)d_in[13];
    const float* W_init_h  = (const float*)d_in[14];
    const float* b_init_h  = (const float*)d_in[15];
    const float* W_init_c  = (const float*)d_in[16];
    const float* b_init_c  = (const float*)d_in[17];
    const float* W_fbeta   = (const float*)d_in[18];
    const float* b_fbeta   = (const float*)d_in[19];
    const float* W_fc      = (const float*)d_in[20];
    const float* b_fc      = (const float*)d_in[21];

    float* out = (float*)d_out;
    float* alpha_out = out + (size_t)BB * TT * VV;

    void* sp = nullptr;
    cudaGetSymbolAddress(&sp, g_scratch);
    float* S = (float*)sp;

    cudaFuncSetAttribute(gemm2<0>, cudaFuncAttributeMaxDynamicSharedMemorySize, G2_SMEM_BYTES);
    cudaFuncSetAttribute(gemm2<1>, cudaFuncAttributeMaxDynamicSharedMemorySize, G2_SMEM_BYTES);
    cudaFuncSetAttribute(gemm2<2>, cudaFuncAttributeMaxDynamicSharedMemorySize, G2_SMEM_BYTES);
    cudaFuncSetAttribute(recur_kernel, cudaFuncAttributeMaxDynamicSharedMemorySize, RSMEM_BYTES);

    // 1. prep
    prep_kernel<<<2048, 256>>>(W_dec_att, W_fbeta, b_dec_att, b_fbeta, W_ih, W_hh, b_ih, b_hh,
                               enc, emb, W_fc, W_enc_att, W_init_h, W_init_c,
                               b_init_h, b_init_c, caps);

    // 2. [h0 | c0] = mean @ W0 + b0 (split epilogue)
    gemm2<2><<<dim3(16, 1), 256, G2_SMEM_BYTES>>>(
        (const __half*)(S + OFF_MEAN), ENC, (const __half*)(S + OFF_W0), 2048,
        S, 0, S + OFF_B0, BB, 2048, ENC);

    // 3. att_enc = enc_h @ W_enc_h + b_enc_att
    gemm2<0><<<dim3(4, 98), 256, G2_SMEM_BYTES>>>(
        (const __half*)(S + OFF_ENC_H), ENC, (const __half*)(S + OFF_WEA_H), AA,
        S + OFF_ATT_ENC, AA, b_enc_att, BB * PP, AA, ENC);

    // 4. ebias = embg @ Wih_perm + brec
    gemm2<0><<<dim3(32, 12), 256, G2_SMEM_BYTES>>>(
        (const __half*)(S + OFF_EMBG), EE, (const __half*)(S + OFF_WIH), 4096,
        S + OFF_EBIAS, 4096, S + OFF_BREC, TT * BB, 4096, EE);

    // 5. persistent 24-step recurrence
    recur_kernel<<<NBLK, 256, RSMEM_BYTES>>>(enc, W_full, b_full, alpha_out);

    // 6. predictions = hall @ W_fc_h + b_fc (remapped to (B,T,V))
    gemm2<1><<<dim3(157, 12), 256, G2_SMEM_BYTES>>>(
        (const __half*)(S + OFF_HALL), HH, (const __half*)(S + OFF_WFC_H), VV,
        out, VV, b_fc, TT * BB, VV, HH);
}